// round 5
// baseline (speedup 1.0000x reference)
#include <cuda_runtime.h>
#include <math.h>

#define B_ 8
#define T_ 512
#define C_ 512
#define H_ 8
#define F_ 2048
#define WIN_ 10
#define TP_ 516

#define ELT_X (B_*C_*T_)
#define ELT_P (B_*H_*T_*T_)
#define ELT_XP (B_*C_*TP_)
#define ELT_HP (B_*F_*TP_)
#define WQKV ((size_t)6*C_*C_)
#define WFF  ((size_t)6*F_*C_*3)

__device__ float g_pool[(size_t)7*ELT_X + ELT_P + ELT_XP + ELT_HP + 4*WQKV + 2*WFF];

__device__ __forceinline__ unsigned f2tf(float x){
    unsigned y; asm("cvt.rna.tf32.f32 %0, %1;" : "=r"(y) : "f"(x)); return y;
}
__device__ __forceinline__ float f2tfr(float x){ return __uint_as_float(f2tf(x)); }
__device__ __forceinline__ void mma_tf32(float c[4], const unsigned a[4], const unsigned b[2]){
    asm("mma.sync.aligned.m16n8k8.row.col.f32.tf32.tf32.f32 "
        "{%0,%1,%2,%3}, {%4,%5,%6,%7}, {%8,%9}, {%0,%1,%2,%3};"
        : "+f"(c[0]), "+f"(c[1]), "+f"(c[2]), "+f"(c[3])
        : "r"(a[0]), "r"(a[1]), "r"(a[2]), "r"(a[3]), "r"(b[0]), "r"(b[1]));
}
__device__ __forceinline__ void cp16(void* smem, const void* g){
    unsigned s = (unsigned)__cvta_generic_to_shared(smem);
    asm volatile("cp.async.ca.shared.global [%0], [%1], 16;" :: "r"(s), "l"(g));
}
__device__ __forceinline__ void cp4(void* smem, const void* g){
    unsigned s = (unsigned)__cvta_generic_to_shared(smem);
    asm volatile("cp.async.ca.shared.global [%0], [%1], 4;" :: "r"(s), "l"(g));
}
#define CP_COMMIT asm volatile("cp.async.commit_group;" ::: "memory")
#define CP_WAIT1  asm volatile("cp.async.wait_group 1;" ::: "memory")
#define CP_WAIT0  asm volatile("cp.async.wait_group 0;" ::: "memory")

/* ---------------- tf32 rounding of an array (weights) ---------------- */
__global__ void k_round(const float* __restrict__ S, float* __restrict__ D, int n4)
{
    int i = blockIdx.x*256 + threadIdx.x;
    if (i < n4){
        float4 v = ((const float4*)S)[i];
        v.x=f2tfr(v.x); v.y=f2tfr(v.y); v.z=f2tfr(v.z); v.w=f2tfr(v.w);
        ((float4*)D)[i] = v;
    }
}

/* ---------------- mask, dual output (fp32 + tf32-rounded) ---------------- */
__global__ void k_maskmul2(const float* __restrict__ X, const float* __restrict__ mask,
                           float* __restrict__ Y, float* __restrict__ Yr)
{
    int i = blockIdx.x*256 + threadIdx.x;
    int t = i & (T_-1);
    int b = i / (C_*T_);
    float v = X[i] * mask[b*T_ + t];
    Y[i] = v; Yr[i] = f2tfr(v);
}
__global__ void k_maskmul(const float* __restrict__ X, const float* __restrict__ mask,
                          float* __restrict__ Y)
{
    int i = blockIdx.x*256 + threadIdx.x;
    int t = i & (T_-1);
    int b = i / (C_*T_);
    Y[i] = X[i] * mask[b*T_ + t];
}

/* ---------------- zero pad borders of pxp / php once ---------------- */
__global__ void k_zb(float* __restrict__ Xp, float* __restrict__ Hp)
{
    int r = blockIdx.x*256 + threadIdx.x;
    float* base = (r < B_*C_) ? (Xp + (size_t)r*TP_) : (Hp + (size_t)(r - B_*C_)*TP_);
    base[0]=0.f; base[513]=0.f; base[514]=0.f; base[515]=0.f;
}

/* ======================================================================
   All GEMM kernels: 128x128 block tile, 256 thr, warp tile 64x32,
   3-stage cp.async pipeline, tf32 MMA. Operands pre-rounded to tf32.
   ====================================================================== */

/* =========== 1x1 GEMM (used for Wo): Y[b,o,t] = W X + bias ============ */
__launch_bounds__(256,2)
__global__ void g1x1(const float* __restrict__ X, const float* __restrict__ Wm,
                     const float* __restrict__ bias, float* __restrict__ Y)
{
    const int n0 = blockIdx.x*128;
    const int m0 = blockIdx.y*128;
    const int b  = blockIdx.z;
    const int tid = threadIdx.x;
    const int lane = tid & 31, wid = tid >> 5;
    const int gid = lane >> 2, tig = lane & 3;
    const int wm = wid & 1, wn = wid >> 1;

    __shared__ float smA[3][128][20];
    __shared__ float smB[3][16][136];

    const float* xb = X + (size_t)b*C_*T_;
    const int rowA = tid >> 1, colA = (tid & 1)*8;
    const int rowB = tid >> 4, colB = (tid & 15)*8;

    float acc[4][4][4];
#pragma unroll
    for (int i=0;i<4;i++)
#pragma unroll
        for (int j=0;j<4;j++)
#pragma unroll
            for (int u=0;u<4;u++) acc[i][j][u]=0.f;

    const int KT = C_/16;
#define ST_A(st,K0) { const float* ap = Wm + (size_t)(m0+rowA)*C_ + (K0) + colA; \
                      cp16(&smA[st][rowA][colA], ap); cp16(&smA[st][rowA][colA+4], ap+4); }
#define ST_B(st,K0) { const float* bp = xb + (size_t)((K0)+rowB)*T_ + n0 + colB; \
                      cp16(&smB[st][rowB][colB], bp); cp16(&smB[st][rowB][colB+4], bp+4); }
    ST_A(0,0) ST_B(0,0) CP_COMMIT;
    ST_A(1,16) ST_B(1,16) CP_COMMIT;

    for (int kt=0; kt<KT; kt++){
        if (kt==KT-1) { CP_WAIT0; } else { CP_WAIT1; }
        __syncthreads();
        if (kt+2 < KT){ int st=(kt+2)%3; int K0=(kt+2)*16; ST_A(st,K0) ST_B(st,K0) CP_COMMIT; }
        const int buf = kt%3;
#pragma unroll
        for (int ks=0;ks<2;ks++){
            unsigned af[4][4], bf[4][2];
#pragma unroll
            for (int i=0;i<4;i++){
                int r = wm*64 + i*16 + gid;
                af[i][0]=__float_as_uint(smA[buf][r  ][ks*8+tig  ]);
                af[i][1]=__float_as_uint(smA[buf][r+8][ks*8+tig  ]);
                af[i][2]=__float_as_uint(smA[buf][r  ][ks*8+tig+4]);
                af[i][3]=__float_as_uint(smA[buf][r+8][ks*8+tig+4]);
            }
#pragma unroll
            for (int j=0;j<4;j++){
                int c = wn*32 + j*8 + gid;
                bf[j][0]=__float_as_uint(smB[buf][ks*8+tig  ][c]);
                bf[j][1]=__float_as_uint(smB[buf][ks*8+tig+4][c]);
            }
#pragma unroll
            for (int i=0;i<4;i++)
#pragma unroll
                for (int j=0;j<4;j++) mma_tf32(acc[i][j], af[i], bf[j]);
        }
    }
#undef ST_A
#undef ST_B

#pragma unroll
    for (int i=0;i<4;i++){
        int row = m0 + wm*64 + i*16 + gid;
        float bv0 = bias[row], bv8 = bias[row+8];
        float* y0 = Y + (size_t)(b*C_ + row)*T_;
        float* y8 = Y + (size_t)(b*C_ + row+8)*T_;
#pragma unroll
        for (int j=0;j<4;j++){
            int col = n0 + wn*32 + j*8 + tig*2;
            *(float2*)(y0+col)=make_float2(acc[i][j][0]+bv0, acc[i][j][1]+bv0);
            *(float2*)(y8+col)=make_float2(acc[i][j][2]+bv8, acc[i][j][3]+bv8);
        }
    }
}

/* =========== fused Q/K/V. Q -> [bh][t][d] (x0.125, rounded), K -> [c][t] rounded,
               V -> [bh][s][d] rounded ============ */
__launch_bounds__(256,2)
__global__ void g_qkv(const float* __restrict__ X,
                      const float* __restrict__ Wq, const float* __restrict__ Wk, const float* __restrict__ Wv,
                      const float* __restrict__ bq, const float* __restrict__ bk, const float* __restrict__ bv,
                      float* __restrict__ Yq, float* __restrict__ Yk, float* __restrict__ Yv)
{
    const int n0 = blockIdx.x*128;
    const int mi = blockIdx.y;
    const int sel = mi >> 2;
    const int m0 = (mi & 3)*128;
    const int b  = blockIdx.z;
    const float* Wm  = (sel==0)?Wq:(sel==1)?Wk:Wv;
    const float* bias= (sel==0)?bq:(sel==1)?bk:bv;
    const float alpha= (sel==0)?0.125f:1.f;

    const int tid = threadIdx.x;
    const int lane = tid & 31, wid = tid >> 5;
    const int gid = lane >> 2, tig = lane & 3;
    const int wm = wid & 1, wn = wid >> 1;

    __shared__ float smA[3][128][20];
    __shared__ float smB[3][16][136];

    const float* xb = X + (size_t)b*C_*T_;
    const int rowA = tid >> 1, colA = (tid & 1)*8;
    const int rowB = tid >> 4, colB = (tid & 15)*8;

    float acc[4][4][4];
#pragma unroll
    for (int i=0;i<4;i++)
#pragma unroll
        for (int j=0;j<4;j++)
#pragma unroll
            for (int u=0;u<4;u++) acc[i][j][u]=0.f;

    const int KT = C_/16;
#define ST_A(st,K0) { const float* ap = Wm + (size_t)(m0+rowA)*C_ + (K0) + colA; \
                      cp16(&smA[st][rowA][colA], ap); cp16(&smA[st][rowA][colA+4], ap+4); }
#define ST_B(st,K0) { const float* bp = xb + (size_t)((K0)+rowB)*T_ + n0 + colB; \
                      cp16(&smB[st][rowB][colB], bp); cp16(&smB[st][rowB][colB+4], bp+4); }
    ST_A(0,0) ST_B(0,0) CP_COMMIT;
    ST_A(1,16) ST_B(1,16) CP_COMMIT;

    for (int kt=0; kt<KT; kt++){
        if (kt==KT-1) { CP_WAIT0; } else { CP_WAIT1; }
        __syncthreads();
        if (kt+2 < KT){ int st=(kt+2)%3; int K0=(kt+2)*16; ST_A(st,K0) ST_B(st,K0) CP_COMMIT; }
        const int buf = kt%3;
#pragma unroll
        for (int ks=0;ks<2;ks++){
            unsigned af[4][4], bf[4][2];
#pragma unroll
            for (int i=0;i<4;i++){
                int r = wm*64 + i*16 + gid;
                af[i][0]=__float_as_uint(smA[buf][r  ][ks*8+tig  ]);
                af[i][1]=__float_as_uint(smA[buf][r+8][ks*8+tig  ]);
                af[i][2]=__float_as_uint(smA[buf][r  ][ks*8+tig+4]);
                af[i][3]=__float_as_uint(smA[buf][r+8][ks*8+tig+4]);
            }
#pragma unroll
            for (int j=0;j<4;j++){
                int c = wn*32 + j*8 + gid;
                bf[j][0]=__float_as_uint(smB[buf][ks*8+tig  ][c]);
                bf[j][1]=__float_as_uint(smB[buf][ks*8+tig+4][c]);
            }
#pragma unroll
            for (int i=0;i<4;i++)
#pragma unroll
                for (int j=0;j<4;j++) mma_tf32(acc[i][j], af[i], bf[j]);
        }
    }
#undef ST_A
#undef ST_B

    if (sel==1){
#pragma unroll
        for (int i=0;i<4;i++){
            int row = m0 + wm*64 + i*16 + gid;
            float bv0 = bias[row], bv8 = bias[row+8];
            float* y0 = Yk + (size_t)(b*C_ + row)*T_;
            float* y8 = Yk + (size_t)(b*C_ + row+8)*T_;
#pragma unroll
            for (int j=0;j<4;j++){
                int col = n0 + wn*32 + j*8 + tig*2;
                *(float2*)(y0+col)=make_float2(f2tfr(acc[i][j][0]+bv0), f2tfr(acc[i][j][1]+bv0));
                *(float2*)(y8+col)=make_float2(f2tfr(acc[i][j][2]+bv8), f2tfr(acc[i][j][3]+bv8));
            }
        }
    } else {
        float* Yt = (sel==0)?Yq:Yv;
#pragma unroll
        for (int i=0;i<4;i++){
            int row = m0 + wm*64 + i*16 + gid;
            float bv0 = bias[row], bv8 = bias[row+8];
            int h0 = row>>6, d0v = row&63;
            int h8 = (row+8)>>6, d8v = (row+8)&63;
            float* base0 = Yt + ((size_t)(b*H_+h0)*T_)*64 + d0v;
            float* base8 = Yt + ((size_t)(b*H_+h8)*T_)*64 + d8v;
#pragma unroll
            for (int j=0;j<4;j++){
                int col = n0 + wn*32 + j*8 + tig*2;
                base0[(size_t)col*64]     = f2tfr(alpha*(acc[i][j][0]+bv0));
                base0[(size_t)(col+1)*64] = f2tfr(alpha*(acc[i][j][1]+bv0));
                base8[(size_t)col*64]     = f2tfr(alpha*(acc[i][j][2]+bv8));
                base8[(size_t)(col+1)*64] = f2tfr(alpha*(acc[i][j][3]+bv8));
            }
        }
    }
}

/* =========== scores: P[bh,t,s] = sum_d Qt[bh,t,d]*K[bh,d,s] ============ */
__launch_bounds__(256,2)
__global__ void g_sc(const float* __restrict__ Qt, const float* __restrict__ Kc,
                     float* __restrict__ P)
{
    const int s0 = blockIdx.x*128;
    const int t0 = blockIdx.y*128;
    const int bh = blockIdx.z;
    const int tid = threadIdx.x;
    const int lane = tid & 31, wid = tid >> 5;
    const int gid = lane >> 2, tig = lane & 3;
    const int wm = wid & 1, wn = wid >> 1;

    __shared__ float smA[3][128][20];
    __shared__ float smB[3][16][136];

    const float* qb = Qt + (size_t)bh*T_*64;
    const float* kb = Kc + (size_t)bh*64*T_;
    const int rowA = tid >> 1, colA = (tid & 1)*8;
    const int rowB = tid >> 4, colB = (tid & 15)*8;

    float acc[4][4][4];
#pragma unroll
    for (int i=0;i<4;i++)
#pragma unroll
        for (int j=0;j<4;j++)
#pragma unroll
            for (int u=0;u<4;u++) acc[i][j][u]=0.f;

#define ST_A(st,K0) { const float* ap = qb + (size_t)(t0+rowA)*64 + (K0) + colA; \
                      cp16(&smA[st][rowA][colA], ap); cp16(&smA[st][rowA][colA+4], ap+4); }
#define ST_B(st,K0) { const float* bp = kb + (size_t)((K0)+rowB)*T_ + s0 + colB; \
                      cp16(&smB[st][rowB][colB], bp); cp16(&smB[st][rowB][colB+4], bp+4); }
    ST_A(0,0) ST_B(0,0) CP_COMMIT;
    ST_A(1,16) ST_B(1,16) CP_COMMIT;

    for (int kt=0; kt<4; kt++){
        if (kt==3) { CP_WAIT0; } else { CP_WAIT1; }
        __syncthreads();
        if (kt+2 < 4){ int st=(kt+2)%3; int K0=(kt+2)*16; ST_A(st,K0) ST_B(st,K0) CP_COMMIT; }
        const int buf = kt%3;
#pragma unroll
        for (int ks=0;ks<2;ks++){
            unsigned af[4][4], bf[4][2];
#pragma unroll
            for (int i=0;i<4;i++){
                int r = wm*64 + i*16 + gid;
                af[i][0]=__float_as_uint(smA[buf][r  ][ks*8+tig  ]);
                af[i][1]=__float_as_uint(smA[buf][r+8][ks*8+tig  ]);
                af[i][2]=__float_as_uint(smA[buf][r  ][ks*8+tig+4]);
                af[i][3]=__float_as_uint(smA[buf][r+8][ks*8+tig+4]);
            }
#pragma unroll
            for (int j=0;j<4;j++){
                int c = wn*32 + j*8 + gid;
                bf[j][0]=__float_as_uint(smB[buf][ks*8+tig  ][c]);
                bf[j][1]=__float_as_uint(smB[buf][ks*8+tig+4][c]);
            }
#pragma unroll
            for (int i=0;i<4;i++)
#pragma unroll
                for (int j=0;j<4;j++) mma_tf32(acc[i][j], af[i], bf[j]);
        }
    }
#undef ST_A
#undef ST_B

#pragma unroll
    for (int i=0;i<4;i++){
        int row = t0 + wm*64 + i*16 + gid;
        float* y0 = P + ((size_t)bh*T_ + row)*T_;
        float* y8 = P + ((size_t)bh*T_ + row+8)*T_;
#pragma unroll
        for (int j=0;j<4;j++){
            int col = s0 + wn*32 + j*8 + tig*2;
            *(float2*)(y0+col)=make_float2(acc[i][j][0], acc[i][j][1]);
            *(float2*)(y8+col)=make_float2(acc[i][j][2], acc[i][j][3]);
        }
    }
}

/* =========== ctx: CTX[c][t] = sum_s P[t][s] Vt[s][d] + rel-V band ============ */
__launch_bounds__(256,2)
__global__ void g_ctx(const float* __restrict__ P, const float* __restrict__ Vt,
                      const float* __restrict__ erv, float* __restrict__ CTX)
{
    const int t0 = blockIdx.x*128;
    const int bh = blockIdx.y;
    const int b  = bh >> 3, h = bh & 7;
    const int tid = threadIdx.x;
    const int lane = tid & 31, wid = tid >> 5;
    const int gid = lane >> 2, tig = lane & 3;
    const int wm = wid & 1, wn = wid >> 1;

    __shared__ float smA[3][128][20];
    __shared__ float smB[3][16][72];
    __shared__ float sErv[21*64];

    const float* pb = P + (size_t)bh*T_*T_;
    const float* vb = Vt + (size_t)bh*T_*64;
    const int rowA = tid >> 1, colA = (tid & 1)*8;
    const int rowB = tid >> 4, colB = (tid & 15)*4;

    for (int l=tid; l<21*64; l+=256) sErv[l]=erv[l];

    float acc[4][2][4];
#pragma unroll
    for (int i=0;i<4;i++)
#pragma unroll
        for (int j=0;j<2;j++)
#pragma unroll
            for (int u=0;u<4;u++) acc[i][j][u]=0.f;

#define ST_A(st,K0) { const float* ap = pb + (size_t)(t0+rowA)*T_ + (K0) + colA; \
                      cp16(&smA[st][rowA][colA], ap); cp16(&smA[st][rowA][colA+4], ap+4); }
#define ST_B(st,K0) { const float* bp = vb + (size_t)((K0)+rowB)*64 + colB; \
                      cp16(&smB[st][rowB][colB], bp); }
    ST_A(0,0) ST_B(0,0) CP_COMMIT;
    ST_A(1,16) ST_B(1,16) CP_COMMIT;

    const int KT = T_/16;
    for (int kt=0; kt<KT; kt++){
        if (kt==KT-1) { CP_WAIT0; } else { CP_WAIT1; }
        __syncthreads();
        if (kt+2 < KT){ int st=(kt+2)%3; int K0=(kt+2)*16; ST_A(st,K0) ST_B(st,K0) CP_COMMIT; }
        const int buf = kt%3;
#pragma unroll
        for (int ks=0;ks<2;ks++){
            unsigned af[4][4], bf[2][2];
#pragma unroll
            for (int i=0;i<4;i++){
                int r = wm*64 + i*16 + gid;
                af[i][0]=__float_as_uint(smA[buf][r  ][ks*8+tig  ]);
                af[i][1]=__float_as_uint(smA[buf][r+8][ks*8+tig  ]);
                af[i][2]=__float_as_uint(smA[buf][r  ][ks*8+tig+4]);
                af[i][3]=__float_as_uint(smA[buf][r+8][ks*8+tig+4]);
            }
#pragma unroll
            for (int j=0;j<2;j++){
                int c = wn*16 + j*8 + gid;
                bf[j][0]=__float_as_uint(smB[buf][ks*8+tig  ][c]);
                bf[j][1]=__float_as_uint(smB[buf][ks*8+tig+4][c]);
            }
#pragma unroll
            for (int i=0;i<4;i++)
#pragma unroll
                for (int j=0;j<2;j++) mma_tf32(acc[i][j], af[i], bf[j]);
        }
    }
#undef ST_A
#undef ST_B

    /* banded rel-V */
#pragma unroll
    for (int i=0;i<4;i++){
#pragma unroll
        for (int rr=0; rr<2; rr++){
            int t = t0 + wm*64 + i*16 + gid + rr*8;
            const float* prow = pb + (size_t)t*T_;
            for (int r=0;r<21;r++){
                int s = t + r - WIN_;
                if ((unsigned)s < (unsigned)T_){
                    float pv = prow[s];
#pragma unroll
                    for (int j=0;j<2;j++){
                        int d = wn*16 + j*8 + tig*2;
                        acc[i][j][rr*2+0] += pv*sErv[r*64 + d];
                        acc[i][j][rr*2+1] += pv*sErv[r*64 + d+1];
                    }
                }
            }
        }
    }

    /* store transposed rounded: CTX[b][h*64+d][t] */
#pragma unroll
    for (int i=0;i<4;i++){
        int row = t0 + wm*64 + i*16 + gid;
#pragma unroll
        for (int j=0;j<2;j++){
            int d = wn*16 + j*8 + tig*2;
            float* c0 = CTX + (size_t)(b*C_ + h*64 + d)*T_;
            float* c1 = CTX + (size_t)(b*C_ + h*64 + d+1)*T_;
            c0[row]   = f2tfr(acc[i][j][0]);
            c1[row]   = f2tfr(acc[i][j][1]);
            c0[row+8] = f2tfr(acc[i][j][2]);
            c1[row+8] = f2tfr(acc[i][j][3]);
        }
    }
}

/* =========== K=3 conv GEMM on padded pre-rounded input ===========
   mode 0: relu(acc+bias)*mask -> padded rounded output
   mode 1: raw partial -> Y + part*ELT_X (split-K)                 */
__launch_bounds__(256,2)
__global__ void gconv3p(const float* __restrict__ Xp, const float* __restrict__ Wm,
                        const float* __restrict__ bias, const float* __restrict__ mask,
                        float* __restrict__ Y, int Cin, int Cout,
                        int mode, int ktiles)
{
    const int n0 = blockIdx.x*128;
    const int m0 = blockIdx.y*128;
    const int bz = blockIdx.z;
    const int b    = (mode==1) ? (bz & 7) : bz;
    const int part = (mode==1) ? (bz >> 3) : 0;
    const int kOff = part*(ktiles*16);

    const int tid = threadIdx.x;
    const int lane = tid & 31, wid = tid >> 5;
    const int gid = lane >> 2, tig = lane & 3;
    const int wm = wid & 1, wn = wid >> 1;

    __shared__ float smA[3][128][20];
    __shared__ float smB[3][16][136];

    const float* xpb = Xp + (size_t)b*Cin*TP_;
    const int Ktot = Cin*3;
    const int rowA = tid >> 1, colA = (tid & 1)*8;
    const int rowB = tid >> 4, colB = (tid & 15)*8;

    float acc[4][4][4];
#pragma unroll
    for (int i=0;i<4;i++)
#pragma unroll
        for (int j=0;j<4;j++)
#pragma unroll
            for (int u=0;u<4;u++) acc[i][j][u]=0.f;

#define ST_A(st,K0) { const float* ap = Wm + (size_t)(m0+rowA)*Ktot + (K0) + colA; \
                      cp16(&smA[st][rowA][colA], ap); cp16(&smA[st][rowA][colA+4], ap+4); }
#define ST_B(st,K0) { int kg = (K0) + rowB; int cc = kg/3, kk = kg - cc*3; \
                      const float* bp = xpb + (size_t)cc*TP_ + n0 + colB + kk; \
                      _Pragma("unroll") \
                      for (int u=0;u<8;u++) cp4(&smB[st][rowB][colB+u], bp+u); }
    ST_A(0,kOff) ST_B(0,kOff) CP_COMMIT;
    ST_A(1,kOff+16) ST_B(1,kOff+16) CP_COMMIT;

    for (int kt=0; kt<ktiles; kt++){
        if (kt==ktiles-1) { CP_WAIT0; } else { CP_WAIT1; }
        __syncthreads();
        if (kt+2 < ktiles){ int st=(kt+2)%3; int K0=kOff+(kt+2)*16; ST_A(st,K0) ST_B(st,K0) CP_COMMIT; }
        const int buf = kt%3;
#pragma unroll
        for (int ks=0;ks<2;ks++){
            unsigned af[4][4], bf[4][2];
#pragma unroll
            for (int i=0;i<4;i++){
                int r = wm*64 + i*16 + gid;
                af[i][0]=__float_as_uint(smA[buf][r  ][ks*8+tig  ]);
                af[i][1]=__float_as_uint(smA[buf][r+8][ks*8+tig  ]);
                af[i][2]=__float_as_uint(smA[buf][r  ][ks*8+tig+4]);
                af[i][3]=__float_as_uint(smA[buf][r+8][ks*8+tig+4]);
            }
#pragma unroll
            for (int j=0;j<4;j++){
                int c = wn*32 + j*8 + gid;
                bf[j][0]=__float_as_uint(smB[buf][ks*8+tig  ][c]);
                bf[j][1]=__float_as_uint(smB[buf][ks*8+tig+4][c]);
            }
#pragma unroll
            for (int i=0;i<4;i++)
#pragma unroll
                for (int j=0;j<4;j++) mma_tf32(acc[i][j], af[i], bf[j]);
        }
    }
#undef ST_A
#undef ST_B

    if (mode==0){
        const float* mb = mask + b*T_;
#pragma unroll
        for (int i=0;i<4;i++){
            int row = m0 + wm*64 + i*16 + gid;
            float bv0 = bias[row], bv8 = bias[row+8];
            float* y0 = Y + (size_t)(b*Cout + row)*TP_ + 1;
            float* y8 = Y + (size_t)(b*Cout + row+8)*TP_ + 1;
#pragma unroll
            for (int j=0;j<4;j++){
                int col = n0 + wn*32 + j*8 + tig*2;
                float m0v = mb[col], m1v = mb[col+1];
                y0[col]   = f2tfr(fmaxf(acc[i][j][0]+bv0, 0.f)*m0v);
                y0[col+1] = f2tfr(fmaxf(acc[i][j][1]+bv0, 0.f)*m1v);
                y8[col]   = f2tfr(fmaxf(acc[i][j][2]+bv8, 0.f)*m0v);
                y8[col+1] = f2tfr(fmaxf(acc[i][j][3]+bv8, 0.f)*m1v);
            }
        }
    } else {
#pragma unroll
        for (int i=0;i<4;i++){
            int row = m0 + wm*64 + i*16 + gid;
            float* y0 = Y + (size_t)part*ELT_X + (size_t)(b*Cout + row)*T_;
            float* y8 = Y + (size_t)part*ELT_X + (size_t)(b*Cout + row+8)*T_;
#pragma unroll
            for (int j=0;j<4;j++){
                int col = n0 + wn*32 + j*8 + tig*2;
                *(float2*)(y0+col)=make_float2(acc[i][j][0], acc[i][j][1]);
                *(float2*)(y8+col)=make_float2(acc[i][j][2], acc[i][j][3]);
            }
        }
    }
}

/* ---------------- split-K reduce + bias + mask ---------------- */
__global__ void k_red(const float* __restrict__ P0, const float* __restrict__ bias,
                      const float* __restrict__ mask, float* __restrict__ Y)
{
    int i = blockIdx.x*256 + threadIdx.x;
    int t = i & (T_-1);
    int o = (i >> 9) & (C_-1);
    int b = i >> 18;
    Y[i] = (P0[i] + P0[(size_t)ELT_X + i] + bias[o]) * mask[b*T_ + t];
}

/* ---------------- banded relative-K logits (Qt layout) ---------------- */
__global__ void k_relband(const float* __restrict__ Qt, const float* __restrict__ erk,
                          float* __restrict__ P)
{
    const int bh = blockIdx.y;
    const int t = blockIdx.x*8 + (threadIdx.x>>5);
    const int lane = threadIdx.x & 31;
    const float* qr = Qt + ((size_t)bh*T_ + t)*64;
    float q0 = qr[lane];
    float q1 = qr[32+lane];
    float* prow = P + ((size_t)bh*T_ + t)*T_;
    for (int r=0;r<21;r++){
        float pd = q0*erk[r*64+lane] + q1*erk[r*64+32+lane];
#pragma unroll
        for (int o=16;o;o>>=1) pd += __shfl_xor_sync(0xffffffffu, pd, o);
        int s = t + r - WIN_;
        if (lane==0 && (unsigned)s < (unsigned)T_) prow[s] += pd;
    }
}

/* ---------------- row softmax with mask (rounded output) ---------------- */
__launch_bounds__(256)
__global__ void k_softmax(float* __restrict__ P, const float* __restrict__ mask)
{
    const int row = blockIdx.x;
    const int t  = row & (T_-1);
    const int bh = row >> 9;
    const int b  = bh >> 3;
    float* p = P + (size_t)row*T_;
    const float* mb = mask + b*T_;
    const int tid = threadIdx.x;
    const int lane = tid & 31, w = tid >> 5;
    const float mt = mb[t];
    float v0 = (mt*mb[tid]     != 0.f) ? p[tid]     : -1e4f;
    float v1 = (mt*mb[tid+256] != 0.f) ? p[tid+256] : -1e4f;
    __shared__ float red[8];
    float m = fmaxf(v0,v1);
#pragma unroll
    for (int o=16;o;o>>=1) m = fmaxf(m, __shfl_xor_sync(0xffffffffu, m, o));
    if (lane==0) red[w]=m;
    __syncthreads();
    float mx = red[0];
#pragma unroll
    for (int k2=1;k2<8;k2++) mx = fmaxf(mx, red[k2]);
    float e0 = expf(v0-mx), e1 = expf(v1-mx);
    float s = e0+e1;
#pragma unroll
    for (int o=16;o;o>>=1) s += __shfl_xor_sync(0xffffffffu, s, o);
    __syncthreads();
    if (lane==0) red[w]=s;
    __syncthreads();
    float tot = 0.f;
#pragma unroll
    for (int k2=0;k2<8;k2++) tot += red[k2];
    float inv = 1.f/tot;
    p[tid]=f2tfr(e0*inv); p[tid+256]=f2tfr(e1*inv);
}

/* ------- residual add + channel LN; optional padded-rounded / flat-rounded copies -- */
__launch_bounds__(512)
__global__ void k_addln(float* __restrict__ X, const float* __restrict__ Yv,
                        const float* __restrict__ gamma, const float* __restrict__ beta,
                        float* __restrict__ Xp, float* __restrict__ Xr,
                        const float* __restrict__ mask)
{
    const int b = blockIdx.y;
    const int tl = threadIdx.x & 31;
    const int slot = threadIdx.x >> 5;
    const int t = blockIdx.x*32 + tl;
    __shared__ float ssum[16][33];
    __shared__ float ssq[16][33];
    float vals[32];
    float s=0.f, q=0.f;
    size_t base = (size_t)b*C_*T_ + t;
#pragma unroll
    for (int u=0;u<32;u++){
        int c = slot*32+u;
        float v = X[base + (size_t)c*T_] + Yv[base + (size_t)c*T_];
        vals[u]=v; s+=v; q+=v*v;
    }
    ssum[slot][tl]=s; ssq[slot][tl]=q;
    __syncthreads();
    float m=0.f, vv=0.f;
#pragma unroll
    for (int k2=0;k2<16;k2++){ m+=ssum[k2][tl]; vv+=ssq[k2][tl]; }
    m *= (1.f/512.f);
    vv = vv*(1.f/512.f) - m*m;
    float r = rsqrtf(vv + 1e-5f);
    float mk = Xp ? mask[b*T_ + t] : 0.f;
#pragma unroll
    for (int u=0;u<32;u++){
        int c = slot*32+u;
        float o = (vals[u]-m)*r*gamma[c] + beta[c];
        X[base + (size_t)c*T_] = o;
        if (Xp) Xp[((size_t)(b*C_+c))*TP_ + t + 1] = f2tfr(o*mk);
        if (Xr) Xr[base + (size_t)c*T_] = f2tfr(o);
    }
}

/* ---------------- host orchestration ---------------- */
extern "C" void kernel_launch(void* const* d_in, const int* in_sizes, int n_in,
                              void* d_out, int out_size)
{
    (void)in_sizes; (void)n_in; (void)out_size;
    const float* x_in = (const float*)d_in[0];
    const float* mask = (const float*)d_in[1];
    const float* Wq  = (const float*)d_in[2];
    const float* bq  = (const float*)d_in[3];
    const float* Wk  = (const float*)d_in[4];
    const float* bk  = (const float*)d_in[5];
    const float* Wv  = (const float*)d_in[6];
    const float* bv  = (const float*)d_in[7];
    const float* Wo  = (const float*)d_in[8];
    const float* bo  = (const float*)d_in[9];
    const float* erk = (const float*)d_in[10];
    const float* erv = (const float*)d_in[11];
    const float* g1  = (const float*)d_in[12];
    const float* b1  = (const float*)d_in[13];
    const float* g2  = (const float*)d_in[14];
    const float* b2  = (const float*)d_in[15];
    const float* W1  = (const float*)d_in[16];
    const float* bf1 = (const float*)d_in[17];
    const float* W2  = (const float*)d_in[18];
    const float* bf2 = (const float*)d_in[19];

    float* pool = 0;
    cudaGetSymbolAddress((void**)&pool, g_pool);
    float* px  = pool;
    float* pxr = pool + (size_t)1*ELT_X;
    float* pq  = pool + (size_t)2*ELT_X;   /* Qt, also split-K part0 */
    float* pk  = pool + (size_t)3*ELT_X;   /* K,  also split-K part1 */
    float* pv  = pool + (size_t)4*ELT_X;   /* Vt */
    float* pc  = pool + (size_t)5*ELT_X;
    float* py  = pool + (size_t)6*ELT_X;
    float* pp  = pool + (size_t)7*ELT_X;
    float* pxp = pool + (size_t)7*ELT_X + ELT_P;
    float* php = pool + (size_t)7*ELT_X + ELT_P + ELT_XP;
    float* wqr = php + ELT_HP;
    float* wkr = wqr + WQKV;
    float* wvr = wkr + WQKV;
    float* wor = wvr + WQKV;
    float* w1r = wor + WQKV;
    float* w2r = w1r + WFF;

    k_round<<<(int)(WQKV/4+255)/256,256>>>(Wq, wqr, (int)(WQKV/4));
    k_round<<<(int)(WQKV/4+255)/256,256>>>(Wk, wkr, (int)(WQKV/4));
    k_round<<<(int)(WQKV/4+255)/256,256>>>(Wv, wvr, (int)(WQKV/4));
    k_round<<<(int)(WQKV/4+255)/256,256>>>(Wo, wor, (int)(WQKV/4));
    k_round<<<(int)(WFF/4+255)/256,256>>>(W1, w1r, (int)(WFF/4));
    k_round<<<(int)(WFF/4+255)/256,256>>>(W2, w2r, (int)(WFF/4));

    k_maskmul2<<<ELT_X/256,256>>>(x_in, mask, px, pxr);
    k_zb<<<(B_*C_+B_*F_)/256,256>>>(pxp, php);

    for (int L=0;L<6;L++){
        g_qkv<<<dim3(T_/128, 12, B_),256>>>(pxr, wqr + (size_t)L*C_*C_, wkr + (size_t)L*C_*C_,
                                            wvr + (size_t)L*C_*C_,
                                            bq+L*C_, bk+L*C_, bv+L*C_,
                                            pq, pk, pv);
        g_sc<<<dim3(T_/128, T_/128, B_*H_),256>>>(pq, pk, pp);
        k_relband<<<dim3(T_/8, B_*H_),256>>>(pq, erk + L*21*64, pp);
        k_softmax<<<B_*H_*T_,256>>>(pp, mask);
        g_ctx<<<dim3(T_/128, B_*H_),256>>>(pp, pv, erv + L*21*64, pc);
        g1x1<<<dim3(T_/128, C_/128, B_),256>>>(pc, wor + (size_t)L*C_*C_, bo + L*C_, py);
        k_addln<<<dim3(T_/32,B_),512>>>(px, py, g1+L*C_, b1+L*C_, pxp, (float*)0, mask);

        gconv3p<<<dim3(T_/128, F_/128, B_),256>>>(pxp, w1r + (size_t)L*F_*C_*3, bf1+L*F_, mask,
                                                  php, C_, F_, 0, (C_*3)/16);
        gconv3p<<<dim3(T_/128, C_/128, 2*B_),256>>>(php, w2r + (size_t)L*C_*F_*3, bf2+L*C_, mask,
                                                    pq, F_, C_, 1, (F_*3)/32);
        k_red<<<ELT_X/256,256>>>(pq, bf2+L*C_, mask, py);
        k_addln<<<dim3(T_/32,B_),512>>>(px, py, g2+L*C_, b2+L*C_, (float*)0, pxr, mask);
    }
    k_maskmul<<<ELT_X/256,256>>>(px, mask, (float*)d_out);
}

// round 6
// speedup vs baseline: 1.2913x; 1.2913x over previous
#include <cuda_runtime.h>
#include <math.h>

#define B_ 8
#define T_ 512
#define C_ 512
#define H_ 8
#define F_ 2048
#define WIN_ 10
#define TP_ 516

#define ELT_X (B_*C_*T_)
#define ELT_P (B_*H_*T_*T_)
#define ELT_XP (B_*C_*TP_)
#define ELT_HP (B_*F_*TP_)
#define WQKV ((size_t)6*C_*C_)
#define WFF  ((size_t)6*F_*C_*3)

__device__ float g_pool[(size_t)7*ELT_X + ELT_P + ELT_XP + ELT_HP + 4*WQKV + 2*WFF];

__device__ __forceinline__ unsigned f2tf(float x){
    unsigned y; asm("cvt.rna.tf32.f32 %0, %1;" : "=r"(y) : "f"(x)); return y;
}
__device__ __forceinline__ float f2tfr(float x){ return __uint_as_float(f2tf(x)); }
__device__ __forceinline__ void mma_tf32(float c[4], const unsigned a[4], const unsigned b[2]){
    asm("mma.sync.aligned.m16n8k8.row.col.f32.tf32.tf32.f32 "
        "{%0,%1,%2,%3}, {%4,%5,%6,%7}, {%8,%9}, {%0,%1,%2,%3};"
        : "+f"(c[0]), "+f"(c[1]), "+f"(c[2]), "+f"(c[3])
        : "r"(a[0]), "r"(a[1]), "r"(a[2]), "r"(a[3]), "r"(b[0]), "r"(b[1]));
}
__device__ __forceinline__ void cp16(void* smem, const void* g){
    unsigned s = (unsigned)__cvta_generic_to_shared(smem);
    asm volatile("cp.async.ca.shared.global [%0], [%1], 16;" :: "r"(s), "l"(g));
}
#define CP_COMMIT asm volatile("cp.async.commit_group;" ::: "memory")
#define CP_WAIT1  asm volatile("cp.async.wait_group 1;" ::: "memory")
#define CP_WAIT0  asm volatile("cp.async.wait_group 0;" ::: "memory")

/* ---------------- tf32 rounding of an array (weights) ---------------- */
__global__ void k_round(const float* __restrict__ S, float* __restrict__ D, int n4)
{
    int i = blockIdx.x*256 + threadIdx.x;
    if (i < n4){
        float4 v = ((const float4*)S)[i];
        v.x=f2tfr(v.x); v.y=f2tfr(v.y); v.z=f2tfr(v.z); v.w=f2tfr(v.w);
        ((float4*)D)[i] = v;
    }
}

/* ---------------- mask, dual output (fp32 + tf32-rounded) ---------------- */
__global__ void k_maskmul2(const float* __restrict__ X, const float* __restrict__ mask,
                           float* __restrict__ Y, float* __restrict__ Yr)
{
    int i = blockIdx.x*256 + threadIdx.x;
    int t = i & (T_-1);
    int b = i / (C_*T_);
    float v = X[i] * mask[b*T_ + t];
    Y[i] = v; Yr[i] = f2tfr(v);
}
__global__ void k_maskmul(const float* __restrict__ X, const float* __restrict__ mask,
                          float* __restrict__ Y)
{
    int i = blockIdx.x*256 + threadIdx.x;
    int t = i & (T_-1);
    int b = i / (C_*T_);
    Y[i] = X[i] * mask[b*T_ + t];
}

/* ---------------- zero pad borders of pxp / php once ---------------- */
__global__ void k_zb(float* __restrict__ Xp, float* __restrict__ Hp)
{
    int r = blockIdx.x*256 + threadIdx.x;
    float* base = (r < B_*C_) ? (Xp + (size_t)r*TP_) : (Hp + (size_t)(r - B_*C_)*TP_);
    base[0]=0.f; base[513]=0.f; base[514]=0.f; base[515]=0.f;
}

/* =========== 1x1 GEMM (Wo): Y[b,o,t] = W X + bias ============ */
__launch_bounds__(256,2)
__global__ void g1x1(const float* __restrict__ X, const float* __restrict__ Wm,
                     const float* __restrict__ bias, float* __restrict__ Y)
{
    const int n0 = blockIdx.x*128;
    const int m0 = blockIdx.y*128;
    const int b  = blockIdx.z;
    const int tid = threadIdx.x;
    const int lane = tid & 31, wid = tid >> 5;
    const int gid = lane >> 2, tig = lane & 3;
    const int wm = wid & 1, wn = wid >> 1;

    __shared__ float smA[3][128][20];
    __shared__ float smB[3][16][136];

    const float* xb = X + (size_t)b*C_*T_;
    const int rowA = tid >> 1, colA = (tid & 1)*8;
    const int rowB = tid >> 4, colB = (tid & 15)*8;

    float acc[4][4][4];
#pragma unroll
    for (int i=0;i<4;i++)
#pragma unroll
        for (int j=0;j<4;j++)
#pragma unroll
            for (int u=0;u<4;u++) acc[i][j][u]=0.f;

    const int KT = C_/16;
#define ST_A(st,K0) { const float* ap = Wm + (size_t)(m0+rowA)*C_ + (K0) + colA; \
                      cp16(&smA[st][rowA][colA], ap); cp16(&smA[st][rowA][colA+4], ap+4); }
#define ST_B(st,K0) { const float* bp = xb + (size_t)((K0)+rowB)*T_ + n0 + colB; \
                      cp16(&smB[st][rowB][colB], bp); cp16(&smB[st][rowB][colB+4], bp+4); }
    ST_A(0,0) ST_B(0,0) CP_COMMIT;
    ST_A(1,16) ST_B(1,16) CP_COMMIT;

    for (int kt=0; kt<KT; kt++){
        if (kt==KT-1) { CP_WAIT0; } else { CP_WAIT1; }
        __syncthreads();
        if (kt+2 < KT){ int st=(kt+2)%3; int K0=(kt+2)*16; ST_A(st,K0) ST_B(st,K0) CP_COMMIT; }
        const int buf = kt%3;
#pragma unroll
        for (int ks=0;ks<2;ks++){
            unsigned af[4][4], bf[4][2];
#pragma unroll
            for (int i=0;i<4;i++){
                int r = wm*64 + i*16 + gid;
                af[i][0]=__float_as_uint(smA[buf][r  ][ks*8+tig  ]);
                af[i][1]=__float_as_uint(smA[buf][r+8][ks*8+tig  ]);
                af[i][2]=__float_as_uint(smA[buf][r  ][ks*8+tig+4]);
                af[i][3]=__float_as_uint(smA[buf][r+8][ks*8+tig+4]);
            }
#pragma unroll
            for (int j=0;j<4;j++){
                int c = wn*32 + j*8 + gid;
                bf[j][0]=__float_as_uint(smB[buf][ks*8+tig  ][c]);
                bf[j][1]=__float_as_uint(smB[buf][ks*8+tig+4][c]);
            }
#pragma unroll
            for (int i=0;i<4;i++)
#pragma unroll
                for (int j=0;j<4;j++) mma_tf32(acc[i][j], af[i], bf[j]);
        }
    }
#undef ST_A
#undef ST_B

#pragma unroll
    for (int i=0;i<4;i++){
        int row = m0 + wm*64 + i*16 + gid;
        float bv0 = bias[row], bv8 = bias[row+8];
        float* y0 = Y + (size_t)(b*C_ + row)*T_;
        float* y8 = Y + (size_t)(b*C_ + row+8)*T_;
#pragma unroll
        for (int j=0;j<4;j++){
            int col = n0 + wn*32 + j*8 + tig*2;
            *(float2*)(y0+col)=make_float2(acc[i][j][0]+bv0, acc[i][j][1]+bv0);
            *(float2*)(y8+col)=make_float2(acc[i][j][2]+bv8, acc[i][j][3]+bv8);
        }
    }
}

/* =========== fused Q/K/V ============ */
__launch_bounds__(256,2)
__global__ void g_qkv(const float* __restrict__ X,
                      const float* __restrict__ Wq, const float* __restrict__ Wk, const float* __restrict__ Wv,
                      const float* __restrict__ bq, const float* __restrict__ bk, const float* __restrict__ bv,
                      float* __restrict__ Yq, float* __restrict__ Yk, float* __restrict__ Yv)
{
    const int n0 = blockIdx.x*128;
    const int mi = blockIdx.y;
    const int sel = mi >> 2;
    const int m0 = (mi & 3)*128;
    const int b  = blockIdx.z;
    const float* Wm  = (sel==0)?Wq:(sel==1)?Wk:Wv;
    const float* bias= (sel==0)?bq:(sel==1)?bk:bv;
    const float alpha= (sel==0)?0.125f:1.f;

    const int tid = threadIdx.x;
    const int lane = tid & 31, wid = tid >> 5;
    const int gid = lane >> 2, tig = lane & 3;
    const int wm = wid & 1, wn = wid >> 1;

    __shared__ float smA[3][128][20];
    __shared__ float smB[3][16][136];

    const float* xb = X + (size_t)b*C_*T_;
    const int rowA = tid >> 1, colA = (tid & 1)*8;
    const int rowB = tid >> 4, colB = (tid & 15)*8;

    float acc[4][4][4];
#pragma unroll
    for (int i=0;i<4;i++)
#pragma unroll
        for (int j=0;j<4;j++)
#pragma unroll
            for (int u=0;u<4;u++) acc[i][j][u]=0.f;

    const int KT = C_/16;
#define ST_A(st,K0) { const float* ap = Wm + (size_t)(m0+rowA)*C_ + (K0) + colA; \
                      cp16(&smA[st][rowA][colA], ap); cp16(&smA[st][rowA][colA+4], ap+4); }
#define ST_B(st,K0) { const float* bp = xb + (size_t)((K0)+rowB)*T_ + n0 + colB; \
                      cp16(&smB[st][rowB][colB], bp); cp16(&smB[st][rowB][colB+4], bp+4); }
    ST_A(0,0) ST_B(0,0) CP_COMMIT;
    ST_A(1,16) ST_B(1,16) CP_COMMIT;

    for (int kt=0; kt<KT; kt++){
        if (kt==KT-1) { CP_WAIT0; } else { CP_WAIT1; }
        __syncthreads();
        if (kt+2 < KT){ int st=(kt+2)%3; int K0=(kt+2)*16; ST_A(st,K0) ST_B(st,K0) CP_COMMIT; }
        const int buf = kt%3;
#pragma unroll
        for (int ks=0;ks<2;ks++){
            unsigned af[4][4], bf[4][2];
#pragma unroll
            for (int i=0;i<4;i++){
                int r = wm*64 + i*16 + gid;
                af[i][0]=__float_as_uint(smA[buf][r  ][ks*8+tig  ]);
                af[i][1]=__float_as_uint(smA[buf][r+8][ks*8+tig  ]);
                af[i][2]=__float_as_uint(smA[buf][r  ][ks*8+tig+4]);
                af[i][3]=__float_as_uint(smA[buf][r+8][ks*8+tig+4]);
            }
#pragma unroll
            for (int j=0;j<4;j++){
                int c = wn*32 + j*8 + gid;
                bf[j][0]=__float_as_uint(smB[buf][ks*8+tig  ][c]);
                bf[j][1]=__float_as_uint(smB[buf][ks*8+tig+4][c]);
            }
#pragma unroll
            for (int i=0;i<4;i++)
#pragma unroll
                for (int j=0;j<4;j++) mma_tf32(acc[i][j], af[i], bf[j]);
        }
    }
#undef ST_A
#undef ST_B

    if (sel==1){
#pragma unroll
        for (int i=0;i<4;i++){
            int row = m0 + wm*64 + i*16 + gid;
            float bv0 = bias[row], bv8 = bias[row+8];
            float* y0 = Yk + (size_t)(b*C_ + row)*T_;
            float* y8 = Yk + (size_t)(b*C_ + row+8)*T_;
#pragma unroll
            for (int j=0;j<4;j++){
                int col = n0 + wn*32 + j*8 + tig*2;
                *(float2*)(y0+col)=make_float2(f2tfr(acc[i][j][0]+bv0), f2tfr(acc[i][j][1]+bv0));
                *(float2*)(y8+col)=make_float2(f2tfr(acc[i][j][2]+bv8), f2tfr(acc[i][j][3]+bv8));
            }
        }
    } else {
        float* Yt = (sel==0)?Yq:Yv;
#pragma unroll
        for (int i=0;i<4;i++){
            int row = m0 + wm*64 + i*16 + gid;
            float bv0 = bias[row], bv8 = bias[row+8];
            int h0 = row>>6, d0v = row&63;
            int h8 = (row+8)>>6, d8v = (row+8)&63;
            float* base0 = Yt + ((size_t)(b*H_+h0)*T_)*64 + d0v;
            float* base8 = Yt + ((size_t)(b*H_+h8)*T_)*64 + d8v;
#pragma unroll
            for (int j=0;j<4;j++){
                int col = n0 + wn*32 + j*8 + tig*2;
                base0[(size_t)col*64]     = f2tfr(alpha*(acc[i][j][0]+bv0));
                base0[(size_t)(col+1)*64] = f2tfr(alpha*(acc[i][j][1]+bv0));
                base8[(size_t)col*64]     = f2tfr(alpha*(acc[i][j][2]+bv8));
                base8[(size_t)(col+1)*64] = f2tfr(alpha*(acc[i][j][3]+bv8));
            }
        }
    }
}

/* =========== scores ============ */
__launch_bounds__(256,2)
__global__ void g_sc(const float* __restrict__ Qt, const float* __restrict__ Kc,
                     float* __restrict__ P)
{
    const int s0 = blockIdx.x*128;
    const int t0 = blockIdx.y*128;
    const int bh = blockIdx.z;
    const int tid = threadIdx.x;
    const int lane = tid & 31, wid = tid >> 5;
    const int gid = lane >> 2, tig = lane & 3;
    const int wm = wid & 1, wn = wid >> 1;

    __shared__ float smA[3][128][20];
    __shared__ float smB[3][16][136];

    const float* qb = Qt + (size_t)bh*T_*64;
    const float* kb = Kc + (size_t)bh*64*T_;
    const int rowA = tid >> 1, colA = (tid & 1)*8;
    const int rowB = tid >> 4, colB = (tid & 15)*8;

    float acc[4][4][4];
#pragma unroll
    for (int i=0;i<4;i++)
#pragma unroll
        for (int j=0;j<4;j++)
#pragma unroll
            for (int u=0;u<4;u++) acc[i][j][u]=0.f;

#define ST_A(st,K0) { const float* ap = qb + (size_t)(t0+rowA)*64 + (K0) + colA; \
                      cp16(&smA[st][rowA][colA], ap); cp16(&smA[st][rowA][colA+4], ap+4); }
#define ST_B(st,K0) { const float* bp = kb + (size_t)((K0)+rowB)*T_ + s0 + colB; \
                      cp16(&smB[st][rowB][colB], bp); cp16(&smB[st][rowB][colB+4], bp+4); }
    ST_A(0,0) ST_B(0,0) CP_COMMIT;
    ST_A(1,16) ST_B(1,16) CP_COMMIT;

    for (int kt=0; kt<4; kt++){
        if (kt==3) { CP_WAIT0; } else { CP_WAIT1; }
        __syncthreads();
        if (kt+2 < 4){ int st=(kt+2)%3; int K0=(kt+2)*16; ST_A(st,K0) ST_B(st,K0) CP_COMMIT; }
        const int buf = kt%3;
#pragma unroll
        for (int ks=0;ks<2;ks++){
            unsigned af[4][4], bf[4][2];
#pragma unroll
            for (int i=0;i<4;i++){
                int r = wm*64 + i*16 + gid;
                af[i][0]=__float_as_uint(smA[buf][r  ][ks*8+tig  ]);
                af[i][1]=__float_as_uint(smA[buf][r+8][ks*8+tig  ]);
                af[i][2]=__float_as_uint(smA[buf][r  ][ks*8+tig+4]);
                af[i][3]=__float_as_uint(smA[buf][r+8][ks*8+tig+4]);
            }
#pragma unroll
            for (int j=0;j<4;j++){
                int c = wn*32 + j*8 + gid;
                bf[j][0]=__float_as_uint(smB[buf][ks*8+tig  ][c]);
                bf[j][1]=__float_as_uint(smB[buf][ks*8+tig+4][c]);
            }
#pragma unroll
            for (int i=0;i<4;i++)
#pragma unroll
                for (int j=0;j<4;j++) mma_tf32(acc[i][j], af[i], bf[j]);
        }
    }
#undef ST_A
#undef ST_B

#pragma unroll
    for (int i=0;i<4;i++){
        int row = t0 + wm*64 + i*16 + gid;
        float* y0 = P + ((size_t)bh*T_ + row)*T_;
        float* y8 = P + ((size_t)bh*T_ + row+8)*T_;
#pragma unroll
        for (int j=0;j<4;j++){
            int col = s0 + wn*32 + j*8 + tig*2;
            *(float2*)(y0+col)=make_float2(acc[i][j][0], acc[i][j][1]);
            *(float2*)(y8+col)=make_float2(acc[i][j][2], acc[i][j][3]);
        }
    }
}

/* =========== ctx + rel-V band ============ */
__launch_bounds__(256,2)
__global__ void g_ctx(const float* __restrict__ P, const float* __restrict__ Vt,
                      const float* __restrict__ erv, float* __restrict__ CTX)
{
    const int t0 = blockIdx.x*128;
    const int bh = blockIdx.y;
    const int b  = bh >> 3, h = bh & 7;
    const int tid = threadIdx.x;
    const int lane = tid & 31, wid = tid >> 5;
    const int gid = lane >> 2, tig = lane & 3;
    const int wm = wid & 1, wn = wid >> 1;

    __shared__ float smA[3][128][20];
    __shared__ float smB[3][16][72];
    __shared__ float sErv[21*64];

    const float* pb = P + (size_t)bh*T_*T_;
    const float* vb = Vt + (size_t)bh*T_*64;
    const int rowA = tid >> 1, colA = (tid & 1)*8;
    const int rowB = tid >> 4, colB = (tid & 15)*4;

    for (int l=tid; l<21*64; l+=256) sErv[l]=erv[l];

    float acc[4][2][4];
#pragma unroll
    for (int i=0;i<4;i++)
#pragma unroll
        for (int j=0;j<2;j++)
#pragma unroll
            for (int u=0;u<4;u++) acc[i][j][u]=0.f;

#define ST_A(st,K0) { const float* ap = pb + (size_t)(t0+rowA)*T_ + (K0) + colA; \
                      cp16(&smA[st][rowA][colA], ap); cp16(&smA[st][rowA][colA+4], ap+4); }
#define ST_B(st,K0) { const float* bp = vb + (size_t)((K0)+rowB)*64 + colB; \
                      cp16(&smB[st][rowB][colB], bp); }
    ST_A(0,0) ST_B(0,0) CP_COMMIT;
    ST_A(1,16) ST_B(1,16) CP_COMMIT;

    const int KT = T_/16;
    for (int kt=0; kt<KT; kt++){
        if (kt==KT-1) { CP_WAIT0; } else { CP_WAIT1; }
        __syncthreads();
        if (kt+2 < KT){ int st=(kt+2)%3; int K0=(kt+2)*16; ST_A(st,K0) ST_B(st,K0) CP_COMMIT; }
        const int buf = kt%3;
#pragma unroll
        for (int ks=0;ks<2;ks++){
            unsigned af[4][4], bf[2][2];
#pragma unroll
            for (int i=0;i<4;i++){
                int r = wm*64 + i*16 + gid;
                af[i][0]=__float_as_uint(smA[buf][r  ][ks*8+tig  ]);
                af[i][1]=__float_as_uint(smA[buf][r+8][ks*8+tig  ]);
                af[i][2]=__float_as_uint(smA[buf][r  ][ks*8+tig+4]);
                af[i][3]=__float_as_uint(smA[buf][r+8][ks*8+tig+4]);
            }
#pragma unroll
            for (int j=0;j<2;j++){
                int c = wn*16 + j*8 + gid;
                bf[j][0]=__float_as_uint(smB[buf][ks*8+tig  ][c]);
                bf[j][1]=__float_as_uint(smB[buf][ks*8+tig+4][c]);
            }
#pragma unroll
            for (int i=0;i<4;i++)
#pragma unroll
                for (int j=0;j<2;j++) mma_tf32(acc[i][j], af[i], bf[j]);
        }
    }
#undef ST_A
#undef ST_B

#pragma unroll
    for (int i=0;i<4;i++){
#pragma unroll
        for (int rr=0; rr<2; rr++){
            int t = t0 + wm*64 + i*16 + gid + rr*8;
            const float* prow = pb + (size_t)t*T_;
            for (int r=0;r<21;r++){
                int s = t + r - WIN_;
                if ((unsigned)s < (unsigned)T_){
                    float pv = prow[s];
#pragma unroll
                    for (int j=0;j<2;j++){
                        int d = wn*16 + j*8 + tig*2;
                        acc[i][j][rr*2+0] += pv*sErv[r*64 + d];
                        acc[i][j][rr*2+1] += pv*sErv[r*64 + d+1];
                    }
                }
            }
        }
    }

#pragma unroll
    for (int i=0;i<4;i++){
        int row = t0 + wm*64 + i*16 + gid;
#pragma unroll
        for (int j=0;j<2;j++){
            int d = wn*16 + j*8 + tig*2;
            float* c0 = CTX + (size_t)(b*C_ + h*64 + d)*T_;
            float* c1 = CTX + (size_t)(b*C_ + h*64 + d+1)*T_;
            c0[row]   = f2tfr(acc[i][j][0]);
            c1[row]   = f2tfr(acc[i][j][1]);
            c0[row+8] = f2tfr(acc[i][j][2]);
            c1[row+8] = f2tfr(acc[i][j][3]);
        }
    }
}

/* =========== K=3 conv GEMM: raw-row smem staging + shifted fragment loads =======
   B k-tile (16 im2col rows) spans 6 raw x rows; stage those once, resolve the
   k-shift at LDS time: b[kq][n] = smX[kg/3 - cc0][n + kg%3].
   mode 0: relu(acc+bias)*mask -> padded rounded output
   mode 1: raw partial -> Y + part*ELT_X (split-K)                              */
__launch_bounds__(256,2)
__global__ void gconv3p(const float* __restrict__ Xp, const float* __restrict__ Wm,
                        const float* __restrict__ bias, const float* __restrict__ mask,
                        float* __restrict__ Y, int Cin, int Cout,
                        int mode, int ktiles)
{
    const int n0 = blockIdx.x*128;
    const int m0 = blockIdx.y*128;
    const int bz = blockIdx.z;
    const int b    = (mode==1) ? (bz & 7) : bz;
    const int part = (mode==1) ? (bz >> 3) : 0;
    const int kOff = part*(ktiles*16);

    const int tid = threadIdx.x;
    const int lane = tid & 31, wid = tid >> 5;
    const int gid = lane >> 2, tig = lane & 3;
    const int wm = wid & 1, wn = wid >> 1;

    __shared__ float smA[3][128][20];
    __shared__ float smX[3][6][136];   /* smX[r][j] = x[cc0+r][t = n0-1+j] */

    const float* xpb = Xp + (size_t)b*Cin*TP_;
    const int Ktot = Cin*3;
    const int rowA = tid >> 1, colA = (tid & 1)*8;
    const int rB = tid/33, cB = tid - rB*33;   /* 198 loader threads: 6 rows x 33 float4 */

    float acc[4][4][4];
#pragma unroll
    for (int i=0;i<4;i++)
#pragma unroll
        for (int j=0;j<4;j++)
#pragma unroll
            for (int u=0;u<4;u++) acc[i][j][u]=0.f;

#define ST_A(st,K0) { const float* ap = Wm + (size_t)(m0+rowA)*Ktot + (K0) + colA; \
                      cp16(&smA[st][rowA][colA], ap); cp16(&smA[st][rowA][colA+4], ap+4); }
#define ST_B(st,K0) { if (tid < 198){ int cc0 = (K0)/3; \
                      const float* bp = xpb + (size_t)(cc0+rB)*TP_ + n0 + cB*4; \
                      cp16(&smX[st][rB][cB*4], bp); } }
    ST_A(0,kOff) ST_B(0,kOff) CP_COMMIT;
    ST_A(1,kOff+16) ST_B(1,kOff+16) CP_COMMIT;

    for (int kt=0; kt<ktiles; kt++){
        if (kt==ktiles-1) { CP_WAIT0; } else { CP_WAIT1; }
        __syncthreads();
        if (kt+2 < ktiles){ int st=(kt+2)%3; int K0=kOff+(kt+2)*16; ST_A(st,K0) ST_B(st,K0) CP_COMMIT; }
        const int buf = kt%3;
        const int Kbase = kOff + kt*16;
        const int cc0t = Kbase/3;
#pragma unroll
        for (int ks=0;ks<2;ks++){
            int kg0 = Kbase + ks*8 + tig;
            int kg1 = kg0 + 4;
            int q0 = kg0/3, q1 = kg1/3;
            int r0 = q0 - cc0t, k0 = kg0 - q0*3;
            int r1 = q1 - cc0t, k1 = kg1 - q1*3;
            unsigned af[4][4], bf[4][2];
#pragma unroll
            for (int i=0;i<4;i++){
                int r = wm*64 + i*16 + gid;
                af[i][0]=__float_as_uint(smA[buf][r  ][ks*8+tig  ]);
                af[i][1]=__float_as_uint(smA[buf][r+8][ks*8+tig  ]);
                af[i][2]=__float_as_uint(smA[buf][r  ][ks*8+tig+4]);
                af[i][3]=__float_as_uint(smA[buf][r+8][ks*8+tig+4]);
            }
#pragma unroll
            for (int j=0;j<4;j++){
                int c = wn*32 + j*8 + gid;
                bf[j][0]=__float_as_uint(smX[buf][r0][c + k0]);
                bf[j][1]=__float_as_uint(smX[buf][r1][c + k1]);
            }
#pragma unroll
            for (int i=0;i<4;i++)
#pragma unroll
                for (int j=0;j<4;j++) mma_tf32(acc[i][j], af[i], bf[j]);
        }
    }
#undef ST_A
#undef ST_B

    if (mode==0){
        const float* mb = mask + b*T_;
#pragma unroll
        for (int i=0;i<4;i++){
            int row = m0 + wm*64 + i*16 + gid;
            float bv0 = bias[row], bv8 = bias[row+8];
            float* y0 = Y + (size_t)(b*Cout + row)*TP_ + 1;
            float* y8 = Y + (size_t)(b*Cout + row+8)*TP_ + 1;
#pragma unroll
            for (int j=0;j<4;j++){
                int col = n0 + wn*32 + j*8 + tig*2;
                float m0v = mb[col], m1v = mb[col+1];
                y0[col]   = f2tfr(fmaxf(acc[i][j][0]+bv0, 0.f)*m0v);
                y0[col+1] = f2tfr(fmaxf(acc[i][j][1]+bv0, 0.f)*m1v);
                y8[col]   = f2tfr(fmaxf(acc[i][j][2]+bv8, 0.f)*m0v);
                y8[col+1] = f2tfr(fmaxf(acc[i][j][3]+bv8, 0.f)*m1v);
            }
        }
    } else {
#pragma unroll
        for (int i=0;i<4;i++){
            int row = m0 + wm*64 + i*16 + gid;
            float* y0 = Y + (size_t)part*ELT_X + (size_t)(b*Cout + row)*T_;
            float* y8 = Y + (size_t)part*ELT_X + (size_t)(b*Cout + row+8)*T_;
#pragma unroll
            for (int j=0;j<4;j++){
                int col = n0 + wn*32 + j*8 + tig*2;
                *(float2*)(y0+col)=make_float2(acc[i][j][0], acc[i][j][1]);
                *(float2*)(y8+col)=make_float2(acc[i][j][2], acc[i][j][3]);
            }
        }
    }
}

/* ---------------- split-K reduce + bias + mask ---------------- */
__global__ void k_red(const float* __restrict__ P0, const float* __restrict__ bias,
                      const float* __restrict__ mask, float* __restrict__ Y)
{
    int i = blockIdx.x*256 + threadIdx.x;
    int t = i & (T_-1);
    int o = (i >> 9) & (C_-1);
    int b = i >> 18;
    Y[i] = (P0[i] + P0[(size_t)ELT_X + i] + bias[o]) * mask[b*T_ + t];
}

/* ---------------- banded relative-K logits (Qt layout) ---------------- */
__global__ void k_relband(const float* __restrict__ Qt, const float* __restrict__ erk,
                          float* __restrict__ P)
{
    const int bh = blockIdx.y;
    const int t = blockIdx.x*8 + (threadIdx.x>>5);
    const int lane = threadIdx.x & 31;
    const float* qr = Qt + ((size_t)bh*T_ + t)*64;
    float q0 = qr[lane];
    float q1 = qr[32+lane];
    float* prow = P + ((size_t)bh*T_ + t)*T_;
    for (int r=0;r<21;r++){
        float pd = q0*erk[r*64+lane] + q1*erk[r*64+32+lane];
#pragma unroll
        for (int o=16;o;o>>=1) pd += __shfl_xor_sync(0xffffffffu, pd, o);
        int s = t + r - WIN_;
        if (lane==0 && (unsigned)s < (unsigned)T_) prow[s] += pd;
    }
}

/* ---------------- row softmax with mask (rounded output) ---------------- */
__launch_bounds__(256)
__global__ void k_softmax(float* __restrict__ P, const float* __restrict__ mask)
{
    const int row = blockIdx.x;
    const int t  = row & (T_-1);
    const int bh = row >> 9;
    const int b  = bh >> 3;
    float* p = P + (size_t)row*T_;
    const float* mb = mask + b*T_;
    const int tid = threadIdx.x;
    const int lane = tid & 31, w = tid >> 5;
    const float mt = mb[t];
    float v0 = (mt*mb[tid]     != 0.f) ? p[tid]     : -1e4f;
    float v1 = (mt*mb[tid+256] != 0.f) ? p[tid+256] : -1e4f;
    __shared__ float red[8];
    float m = fmaxf(v0,v1);
#pragma unroll
    for (int o=16;o;o>>=1) m = fmaxf(m, __shfl_xor_sync(0xffffffffu, m, o));
    if (lane==0) red[w]=m;
    __syncthreads();
    float mx = red[0];
#pragma unroll
    for (int k2=1;k2<8;k2++) mx = fmaxf(mx, red[k2]);
    float e0 = expf(v0-mx), e1 = expf(v1-mx);
    float s = e0+e1;
#pragma unroll
    for (int o=16;o;o>>=1) s += __shfl_xor_sync(0xffffffffu, s, o);
    __syncthreads();
    if (lane==0) red[w]=s;
    __syncthreads();
    float tot = 0.f;
#pragma unroll
    for (int k2=0;k2<8;k2++) tot += red[k2];
    float inv = 1.f/tot;
    p[tid]=f2tfr(e0*inv); p[tid+256]=f2tfr(e1*inv);
}

/* ------- residual add + channel LN; optional padded-rounded / flat-rounded copies -- */
__launch_bounds__(512)
__global__ void k_addln(float* __restrict__ X, const float* __restrict__ Yv,
                        const float* __restrict__ gamma, const float* __restrict__ beta,
                        float* __restrict__ Xp, float* __restrict__ Xr,
                        const float* __restrict__ mask)
{
    const int b = blockIdx.y;
    const int tl = threadIdx.x & 31;
    const int slot = threadIdx.x >> 5;
    const int t = blockIdx.x*32 + tl;
    __shared__ float ssum[16][33];
    __shared__ float ssq[16][33];
    float vals[32];
    float s=0.f, q=0.f;
    size_t base = (size_t)b*C_*T_ + t;
#pragma unroll
    for (int u=0;u<32;u++){
        int c = slot*32+u;
        float v = X[base + (size_t)c*T_] + Yv[base + (size_t)c*T_];
        vals[u]=v; s+=v; q+=v*v;
    }
    ssum[slot][tl]=s; ssq[slot][tl]=q;
    __syncthreads();
    float m=0.f, vv=0.f;
#pragma unroll
    for (int k2=0;k2<16;k2++){ m+=ssum[k2][tl]; vv+=ssq[k2][tl]; }
    m *= (1.f/512.f);
    vv = vv*(1.f/512.f) - m*m;
    float r = rsqrtf(vv + 1e-5f);
    float mk = Xp ? mask[b*T_ + t] : 0.f;
#pragma unroll
    for (int u=0;u<32;u++){
        int c = slot*32+u;
        float o = (vals[u]-m)*r*gamma[c] + beta[c];
        X[base + (size_t)c*T_] = o;
        if (Xp) Xp[((size_t)(b*C_+c))*TP_ + t + 1] = f2tfr(o*mk);
        if (Xr) Xr[base + (size_t)c*T_] = f2tfr(o);
    }
}

/* ---------------- host orchestration ---------------- */
extern "C" void kernel_launch(void* const* d_in, const int* in_sizes, int n_in,
                              void* d_out, int out_size)
{
    (void)in_sizes; (void)n_in; (void)out_size;
    const float* x_in = (const float*)d_in[0];
    const float* mask = (const float*)d_in[1];
    const float* Wq  = (const float*)d_in[2];
    const float* bq  = (const float*)d_in[3];
    const float* Wk  = (const float*)d_in[4];
    const float* bk  = (const float*)d_in[5];
    const float* Wv  = (const float*)d_in[6];
    const float* bv  = (const float*)d_in[7];
    const float* Wo  = (const float*)d_in[8];
    const float* bo  = (const float*)d_in[9];
    const float* erk = (const float*)d_in[10];
    const float* erv = (const float*)d_in[11];
    const float* g1  = (const float*)d_in[12];
    const float* b1  = (const float*)d_in[13];
    const float* g2  = (const float*)d_in[14];
    const float* b2  = (const float*)d_in[15];
    const float* W1  = (const float*)d_in[16];
    const float* bf1 = (const float*)d_in[17];
    const float* W2  = (const float*)d_in[18];
    const float* bf2 = (const float*)d_in[19];

    float* pool = 0;
    cudaGetSymbolAddress((void**)&pool, g_pool);
    float* px  = pool;
    float* pxr = pool + (size_t)1*ELT_X;
    float* pq  = pool + (size_t)2*ELT_X;   /* Qt, also split-K part0 */
    float* pk  = pool + (size_t)3*ELT_X;   /* K,  also split-K part1 */
    float* pv  = pool + (size_t)4*ELT_X;   /* Vt */
    float* pc  = pool + (size_t)5*ELT_X;
    float* py  = pool + (size_t)6*ELT_X;
    float* pp  = pool + (size_t)7*ELT_X;
    float* pxp = pool + (size_t)7*ELT_X + ELT_P;
    float* php = pool + (size_t)7*ELT_X + ELT_P + ELT_XP;
    float* wqr = php + ELT_HP;
    float* wkr = wqr + WQKV;
    float* wvr = wkr + WQKV;
    float* wor = wvr + WQKV;
    float* w1r = wor + WQKV;
    float* w2r = w1r + WFF;

    k_round<<<(int)(WQKV/4+255)/256,256>>>(Wq, wqr, (int)(WQKV/4));
    k_round<<<(int)(WQKV/4+255)/256,256>>>(Wk, wkr, (int)(WQKV/4));
    k_round<<<(int)(WQKV/4+255)/256,256>>>(Wv, wvr, (int)(WQKV/4));
    k_round<<<(int)(WQKV/4+255)/256,256>>>(Wo, wor, (int)(WQKV/4));
    k_round<<<(int)(WFF/4+255)/256,256>>>(W1, w1r, (int)(WFF/4));
    k_round<<<(int)(WFF/4+255)/256,256>>>(W2, w2r, (int)(WFF/4));

    k_maskmul2<<<ELT_X/256,256>>>(x_in, mask, px, pxr);
    k_zb<<<(B_*C_+B_*F_)/256,256>>>(pxp, php);

    for (int L=0;L<6;L++){
        g_qkv<<<dim3(T_/128, 12, B_),256>>>(pxr, wqr + (size_t)L*C_*C_, wkr + (size_t)L*C_*C_,
                                            wvr + (size_t)L*C_*C_,
                                            bq+L*C_, bk+L*C_, bv+L*C_,
                                            pq, pk, pv);
        g_sc<<<dim3(T_/128, T_/128, B_*H_),256>>>(pq, pk, pp);
        k_relband<<<dim3(T_/8, B_*H_),256>>>(pq, erk + L*21*64, pp);
        k_softmax<<<B_*H_*T_,256>>>(pp, mask);
        g_ctx<<<dim3(T_/128, B_*H_),256>>>(pp, pv, erv + L*21*64, pc);
        g1x1<<<dim3(T_/128, C_/128, B_),256>>>(pc, wor + (size_t)L*C_*C_, bo + L*C_, py);
        k_addln<<<dim3(T_/32,B_),512>>>(px, py, g1+L*C_, b1+L*C_, pxp, (float*)0, mask);

        gconv3p<<<dim3(T_/128, F_/128, B_),256>>>(pxp, w1r + (size_t)L*F_*C_*3, bf1+L*F_, mask,
                                                  php, C_, F_, 0, (C_*3)/16);
        gconv3p<<<dim3(T_/128, C_/128, 2*B_),256>>>(php, w2r + (size_t)L*C_*F_*3, bf2+L*C_, mask,
                                                    pq, F_, C_, 1, (F_*3)/32);
        k_red<<<ELT_X/256,256>>>(pq, bf2+L*C_, mask, py);
        k_addln<<<dim3(T_/32,B_),512>>>(px, py, g2+L*C_, b2+L*C_, (float*)0, pxr, mask);
    }
    k_maskmul<<<ELT_X/256,256>>>(px, mask, (float*)d_out);
}

// round 7
// speedup vs baseline: 1.4578x; 1.1290x over previous
#include <cuda_runtime.h>
#include <math.h>

#define B_ 8
#define T_ 512
#define C_ 512
#define H_ 8
#define F_ 2048
#define WIN_ 10
#define TP_ 516

#define ELT_X (B_*C_*T_)
#define ELT_P (B_*H_*T_*T_)
#define ELT_XP (B_*C_*TP_)
#define ELT_HP (B_*F_*TP_)
#define WQKV ((size_t)6*C_*C_)
#define WFF  ((size_t)6*F_*C_*3)

__device__ float g_pool[(size_t)7*ELT_X + ELT_P + ELT_XP + ELT_HP + 4*WQKV + 2*WFF];

__device__ __forceinline__ unsigned f2tf(float x){
    unsigned y; asm("cvt.rna.tf32.f32 %0, %1;" : "=r"(y) : "f"(x)); return y;
}
__device__ __forceinline__ float f2tfr(float x){ return __uint_as_float(f2tf(x)); }
__device__ __forceinline__ void mma_tf32(float c[4], const unsigned a[4], const unsigned b[2]){
    asm("mma.sync.aligned.m16n8k8.row.col.f32.tf32.tf32.f32 "
        "{%0,%1,%2,%3}, {%4,%5,%6,%7}, {%8,%9}, {%0,%1,%2,%3};"
        : "+f"(c[0]), "+f"(c[1]), "+f"(c[2]), "+f"(c[3])
        : "r"(a[0]), "r"(a[1]), "r"(a[2]), "r"(a[3]), "r"(b[0]), "r"(b[1]));
}
__device__ __forceinline__ void cp16(void* smem, const void* g){
    unsigned s = (unsigned)__cvta_generic_to_shared(smem);
    asm volatile("cp.async.ca.shared.global [%0], [%1], 16;" :: "r"(s), "l"(g));
}
#define CP_COMMIT asm volatile("cp.async.commit_group;" ::: "memory")
#define CP_WAIT1  asm volatile("cp.async.wait_group 1;" ::: "memory")
#define CP_WAIT0  asm volatile("cp.async.wait_group 0;" ::: "memory")

/* ------- weight swizzle: [M][Ktot] -> [M/128][Ktot/16][2048] fragment-ready order.
   Within a (128 x 16) k-tile: off = mgrp*256 + ks*128 + lane*4 + u, where the 4
   floats at a lane are A[(mgrp*16+gid+(u&1)*8)][ks*8+tig+(u>>1)*4], lane=gid*4+tig. */
__global__ void k_swizA(const float* __restrict__ S, float* __restrict__ D,
                        int Ktot, size_t msz, size_t total)
{
    size_t idx = (size_t)blockIdx.x*256 + threadIdx.x;
    if (idx >= total) return;
    size_t l = idx / msz;
    int od = (int)(idx - l*msz);
    int mtile = od / (Ktot*128);
    int rem = od - mtile*(Ktot*128);
    int ktile = rem >> 11;
    int rem2 = rem & 2047;
    int mgrp = rem2 >> 8;
    int rem3 = rem2 & 255;
    int ks = rem3 >> 7;
    int rem4 = rem3 & 127;
    int lane4 = rem4 >> 2;
    int u = rem4 & 3;
    int gid = lane4 >> 2, tig = lane4 & 3;
    int m = mtile*128 + mgrp*16 + gid + (u&1)*8;
    int k = ktile*16 + ks*8 + tig + (u>>1)*4;
    D[idx] = f2tfr(S[l*msz + (size_t)m*Ktot + k]);
}

/* ---------------- mask, dual output (fp32 + tf32-rounded) ---------------- */
__global__ void k_maskmul2(const float* __restrict__ X, const float* __restrict__ mask,
                           float* __restrict__ Y, float* __restrict__ Yr)
{
    int i = blockIdx.x*256 + threadIdx.x;
    int t = i & (T_-1);
    int b = i / (C_*T_);
    float v = X[i] * mask[b*T_ + t];
    Y[i] = v; Yr[i] = f2tfr(v);
}
__global__ void k_maskmul(const float* __restrict__ X, const float* __restrict__ mask,
                          float* __restrict__ Y)
{
    int i = blockIdx.x*256 + threadIdx.x;
    int t = i & (T_-1);
    int b = i / (C_*T_);
    Y[i] = X[i] * mask[b*T_ + t];
}

/* ---------------- zero pad borders of pxp / php once ---------------- */
__global__ void k_zb(float* __restrict__ Xp, float* __restrict__ Hp)
{
    int r = blockIdx.x*256 + threadIdx.x;
    float* base = (r < B_*C_) ? (Xp + (size_t)r*TP_) : (Hp + (size_t)(r - B_*C_)*TP_);
    base[0]=0.f; base[513]=0.f; base[514]=0.f; base[515]=0.f;
}

/* fragment-swizzled A load: 1 x LDS.128 */
#define LOAD_AF(af, smAbuf, wm, ks, lane) \
    _Pragma("unroll") \
    for (int i=0;i<4;i++){ \
        const float4 av = *(const float4*)((smAbuf) + ((((wm)*4+i)*2+(ks))<<7) + ((lane)<<2)); \
        af[i][0]=__float_as_uint(av.x); af[i][1]=__float_as_uint(av.y); \
        af[i][2]=__float_as_uint(av.z); af[i][3]=__float_as_uint(av.w); \
    }

/* =========== 1x1 GEMM (Wo): Y[b,o,t] = W X + bias, W pre-swizzled ============ */
__launch_bounds__(256,2)
__global__ void g1x1(const float* __restrict__ Wm, const float* __restrict__ X,
                     const float* __restrict__ bias, float* __restrict__ Y)
{
    const int n0 = blockIdx.x*128;
    const int m0 = blockIdx.y*128;
    const int b  = blockIdx.z;
    const int tid = threadIdx.x;
    const int lane = tid & 31, wid = tid >> 5;
    const int gid = lane >> 2, tig = lane & 3;
    const int wm = wid & 1, wn = wid >> 1;

    __shared__ float smA[3][2048];
    __shared__ float smB[3][16][136];

    const float* xb = X + (size_t)b*C_*T_;
    const int rowB = tid >> 4, colB = (tid & 15)*8;

    float acc[4][4][4];
#pragma unroll
    for (int i=0;i<4;i++)
#pragma unroll
        for (int j=0;j<4;j++)
#pragma unroll
            for (int u=0;u<4;u++) acc[i][j][u]=0.f;

    const int KT = C_/16;
#define ST_A(st,K0) { const float* ap = Wm + (size_t)(m0>>7)*((size_t)C_<<7) + ((size_t)((K0)>>4)<<11) + (tid<<3); \
                      cp16(&smA[st][tid*8], ap); cp16(&smA[st][tid*8+4], ap+4); }
#define ST_B(st,K0) { const float* bp = xb + (size_t)((K0)+rowB)*T_ + n0 + colB; \
                      cp16(&smB[st][rowB][colB], bp); cp16(&smB[st][rowB][colB+4], bp+4); }
    ST_A(0,0) ST_B(0,0) CP_COMMIT;
    ST_A(1,16) ST_B(1,16) CP_COMMIT;

    for (int kt=0; kt<KT; kt++){
        if (kt==KT-1) { CP_WAIT0; } else { CP_WAIT1; }
        __syncthreads();
        if (kt+2 < KT){ int st=(kt+2)%3; int K0=(kt+2)*16; ST_A(st,K0) ST_B(st,K0) CP_COMMIT; }
        const int buf = kt%3;
#pragma unroll
        for (int ks=0;ks<2;ks++){
            unsigned af[4][4], bf[4][2];
            LOAD_AF(af, smA[buf], wm, ks, lane)
#pragma unroll
            for (int j=0;j<4;j++){
                int c = wn*32 + j*8 + gid;
                bf[j][0]=__float_as_uint(smB[buf][ks*8+tig  ][c]);
                bf[j][1]=__float_as_uint(smB[buf][ks*8+tig+4][c]);
            }
#pragma unroll
            for (int i=0;i<4;i++)
#pragma unroll
                for (int j=0;j<4;j++) mma_tf32(acc[i][j], af[i], bf[j]);
        }
    }
#undef ST_A
#undef ST_B

#pragma unroll
    for (int i=0;i<4;i++){
        int row = m0 + wm*64 + i*16 + gid;
        float bv0 = bias[row], bv8 = bias[row+8];
        float* y0 = Y + (size_t)(b*C_ + row)*T_;
        float* y8 = Y + (size_t)(b*C_ + row+8)*T_;
#pragma unroll
        for (int j=0;j<4;j++){
            int col = n0 + wn*32 + j*8 + tig*2;
            *(float2*)(y0+col)=make_float2(acc[i][j][0]+bv0, acc[i][j][1]+bv0);
            *(float2*)(y8+col)=make_float2(acc[i][j][2]+bv8, acc[i][j][3]+bv8);
        }
    }
}

/* =========== fused Q/K/V, weights pre-swizzled ============ */
__launch_bounds__(256,2)
__global__ void g_qkv(const float* __restrict__ X,
                      const float* __restrict__ Wq, const float* __restrict__ Wk, const float* __restrict__ Wv,
                      const float* __restrict__ bq, const float* __restrict__ bk, const float* __restrict__ bv,
                      float* __restrict__ Yq, float* __restrict__ Yk, float* __restrict__ Yv)
{
    const int n0 = blockIdx.x*128;
    const int mi = blockIdx.y;
    const int sel = mi >> 2;
    const int m0 = (mi & 3)*128;
    const int b  = blockIdx.z;
    const float* Wm  = (sel==0)?Wq:(sel==1)?Wk:Wv;
    const float* bias= (sel==0)?bq:(sel==1)?bk:bv;
    const float alpha= (sel==0)?0.125f:1.f;

    const int tid = threadIdx.x;
    const int lane = tid & 31, wid = tid >> 5;
    const int gid = lane >> 2, tig = lane & 3;
    const int wm = wid & 1, wn = wid >> 1;

    __shared__ float smA[3][2048];
    __shared__ float smB[3][16][136];

    const float* xb = X + (size_t)b*C_*T_;
    const int rowB = tid >> 4, colB = (tid & 15)*8;

    float acc[4][4][4];
#pragma unroll
    for (int i=0;i<4;i++)
#pragma unroll
        for (int j=0;j<4;j++)
#pragma unroll
            for (int u=0;u<4;u++) acc[i][j][u]=0.f;

    const int KT = C_/16;
#define ST_A(st,K0) { const float* ap = Wm + (size_t)(m0>>7)*((size_t)C_<<7) + ((size_t)((K0)>>4)<<11) + (tid<<3); \
                      cp16(&smA[st][tid*8], ap); cp16(&smA[st][tid*8+4], ap+4); }
#define ST_B(st,K0) { const float* bp = xb + (size_t)((K0)+rowB)*T_ + n0 + colB; \
                      cp16(&smB[st][rowB][colB], bp); cp16(&smB[st][rowB][colB+4], bp+4); }
    ST_A(0,0) ST_B(0,0) CP_COMMIT;
    ST_A(1,16) ST_B(1,16) CP_COMMIT;

    for (int kt=0; kt<KT; kt++){
        if (kt==KT-1) { CP_WAIT0; } else { CP_WAIT1; }
        __syncthreads();
        if (kt+2 < KT){ int st=(kt+2)%3; int K0=(kt+2)*16; ST_A(st,K0) ST_B(st,K0) CP_COMMIT; }
        const int buf = kt%3;
#pragma unroll
        for (int ks=0;ks<2;ks++){
            unsigned af[4][4], bf[4][2];
            LOAD_AF(af, smA[buf], wm, ks, lane)
#pragma unroll
            for (int j=0;j<4;j++){
                int c = wn*32 + j*8 + gid;
                bf[j][0]=__float_as_uint(smB[buf][ks*8+tig  ][c]);
                bf[j][1]=__float_as_uint(smB[buf][ks*8+tig+4][c]);
            }
#pragma unroll
            for (int i=0;i<4;i++)
#pragma unroll
                for (int j=0;j<4;j++) mma_tf32(acc[i][j], af[i], bf[j]);
        }
    }
#undef ST_A
#undef ST_B

    if (sel==1){
#pragma unroll
        for (int i=0;i<4;i++){
            int row = m0 + wm*64 + i*16 + gid;
            float bv0 = bias[row], bv8 = bias[row+8];
            float* y0 = Yk + (size_t)(b*C_ + row)*T_;
            float* y8 = Yk + (size_t)(b*C_ + row+8)*T_;
#pragma unroll
            for (int j=0;j<4;j++){
                int col = n0 + wn*32 + j*8 + tig*2;
                *(float2*)(y0+col)=make_float2(f2tfr(acc[i][j][0]+bv0), f2tfr(acc[i][j][1]+bv0));
                *(float2*)(y8+col)=make_float2(f2tfr(acc[i][j][2]+bv8), f2tfr(acc[i][j][3]+bv8));
            }
        }
    } else {
        float* Yt = (sel==0)?Yq:Yv;
#pragma unroll
        for (int i=0;i<4;i++){
            int row = m0 + wm*64 + i*16 + gid;
            float bv0 = bias[row], bv8 = bias[row+8];
            int h0 = row>>6, d0v = row&63;
            int h8 = (row+8)>>6, d8v = (row+8)&63;
            float* base0 = Yt + ((size_t)(b*H_+h0)*T_)*64 + d0v;
            float* base8 = Yt + ((size_t)(b*H_+h8)*T_)*64 + d8v;
#pragma unroll
            for (int j=0;j<4;j++){
                int col = n0 + wn*32 + j*8 + tig*2;
                base0[(size_t)col*64]     = f2tfr(alpha*(acc[i][j][0]+bv0));
                base0[(size_t)(col+1)*64] = f2tfr(alpha*(acc[i][j][1]+bv0));
                base8[(size_t)col*64]     = f2tfr(alpha*(acc[i][j][2]+bv8));
                base8[(size_t)(col+1)*64] = f2tfr(alpha*(acc[i][j][3]+bv8));
            }
        }
    }
}

/* =========== scores (dynamic A: unswizzled path) ============ */
__launch_bounds__(256,2)
__global__ void g_sc(const float* __restrict__ Qt, const float* __restrict__ Kc,
                     float* __restrict__ P)
{
    const int s0 = blockIdx.x*128;
    const int t0 = blockIdx.y*128;
    const int bh = blockIdx.z;
    const int tid = threadIdx.x;
    const int lane = tid & 31, wid = tid >> 5;
    const int gid = lane >> 2, tig = lane & 3;
    const int wm = wid & 1, wn = wid >> 1;

    __shared__ float smA[3][128][20];
    __shared__ float smB[3][16][136];

    const float* qb = Qt + (size_t)bh*T_*64;
    const float* kb = Kc + (size_t)bh*64*T_;
    const int rowA = tid >> 1, colA = (tid & 1)*8;
    const int rowB = tid >> 4, colB = (tid & 15)*8;

    float acc[4][4][4];
#pragma unroll
    for (int i=0;i<4;i++)
#pragma unroll
        for (int j=0;j<4;j++)
#pragma unroll
            for (int u=0;u<4;u++) acc[i][j][u]=0.f;

#define ST_A(st,K0) { const float* ap = qb + (size_t)(t0+rowA)*64 + (K0) + colA; \
                      cp16(&smA[st][rowA][colA], ap); cp16(&smA[st][rowA][colA+4], ap+4); }
#define ST_B(st,K0) { const float* bp = kb + (size_t)((K0)+rowB)*T_ + s0 + colB; \
                      cp16(&smB[st][rowB][colB], bp); cp16(&smB[st][rowB][colB+4], bp+4); }
    ST_A(0,0) ST_B(0,0) CP_COMMIT;
    ST_A(1,16) ST_B(1,16) CP_COMMIT;

    for (int kt=0; kt<4; kt++){
        if (kt==3) { CP_WAIT0; } else { CP_WAIT1; }
        __syncthreads();
        if (kt+2 < 4){ int st=(kt+2)%3; int K0=(kt+2)*16; ST_A(st,K0) ST_B(st,K0) CP_COMMIT; }
        const int buf = kt%3;
#pragma unroll
        for (int ks=0;ks<2;ks++){
            unsigned af[4][4], bf[4][2];
#pragma unroll
            for (int i=0;i<4;i++){
                int r = wm*64 + i*16 + gid;
                af[i][0]=__float_as_uint(smA[buf][r  ][ks*8+tig  ]);
                af[i][1]=__float_as_uint(smA[buf][r+8][ks*8+tig  ]);
                af[i][2]=__float_as_uint(smA[buf][r  ][ks*8+tig+4]);
                af[i][3]=__float_as_uint(smA[buf][r+8][ks*8+tig+4]);
            }
#pragma unroll
            for (int j=0;j<4;j++){
                int c = wn*32 + j*8 + gid;
                bf[j][0]=__float_as_uint(smB[buf][ks*8+tig  ][c]);
                bf[j][1]=__float_as_uint(smB[buf][ks*8+tig+4][c]);
            }
#pragma unroll
            for (int i=0;i<4;i++)
#pragma unroll
                for (int j=0;j<4;j++) mma_tf32(acc[i][j], af[i], bf[j]);
        }
    }
#undef ST_A
#undef ST_B

#pragma unroll
    for (int i=0;i<4;i++){
        int row = t0 + wm*64 + i*16 + gid;
        float* y0 = P + ((size_t)bh*T_ + row)*T_;
        float* y8 = P + ((size_t)bh*T_ + row+8)*T_;
#pragma unroll
        for (int j=0;j<4;j++){
            int col = s0 + wn*32 + j*8 + tig*2;
            *(float2*)(y0+col)=make_float2(acc[i][j][0], acc[i][j][1]);
            *(float2*)(y8+col)=make_float2(acc[i][j][2], acc[i][j][3]);
        }
    }
}

/* =========== ctx + rel-V band (dynamic A: unswizzled path) ============ */
__launch_bounds__(256,2)
__global__ void g_ctx(const float* __restrict__ P, const float* __restrict__ Vt,
                      const float* __restrict__ erv, float* __restrict__ CTX)
{
    const int t0 = blockIdx.x*128;
    const int bh = blockIdx.y;
    const int b  = bh >> 3, h = bh & 7;
    const int tid = threadIdx.x;
    const int lane = tid & 31, wid = tid >> 5;
    const int gid = lane >> 2, tig = lane & 3;
    const int wm = wid & 1, wn = wid >> 1;

    __shared__ float smA[3][128][20];
    __shared__ float smB[3][16][72];
    __shared__ float sErv[21*64];

    const float* pb = P + (size_t)bh*T_*T_;
    const float* vb = Vt + (size_t)bh*T_*64;
    const int rowA = tid >> 1, colA = (tid & 1)*8;
    const int rowB = tid >> 4, colB = (tid & 15)*4;

    for (int l=tid; l<21*64; l+=256) sErv[l]=erv[l];

    float acc[4][2][4];
#pragma unroll
    for (int i=0;i<4;i++)
#pragma unroll
        for (int j=0;j<2;j++)
#pragma unroll
            for (int u=0;u<4;u++) acc[i][j][u]=0.f;

#define ST_A(st,K0) { const float* ap = pb + (size_t)(t0+rowA)*T_ + (K0) + colA; \
                      cp16(&smA[st][rowA][colA], ap); cp16(&smA[st][rowA][colA+4], ap+4); }
#define ST_B(st,K0) { const float* bp = vb + (size_t)((K0)+rowB)*64 + colB; \
                      cp16(&smB[st][rowB][colB], bp); }
    ST_A(0,0) ST_B(0,0) CP_COMMIT;
    ST_A(1,16) ST_B(1,16) CP_COMMIT;

    const int KT = T_/16;
    for (int kt=0; kt<KT; kt++){
        if (kt==KT-1) { CP_WAIT0; } else { CP_WAIT1; }
        __syncthreads();
        if (kt+2 < KT){ int st=(kt+2)%3; int K0=(kt+2)*16; ST_A(st,K0) ST_B(st,K0) CP_COMMIT; }
        const int buf = kt%3;
#pragma unroll
        for (int ks=0;ks<2;ks++){
            unsigned af[4][4], bf[2][2];
#pragma unroll
            for (int i=0;i<4;i++){
                int r = wm*64 + i*16 + gid;
                af[i][0]=__float_as_uint(smA[buf][r  ][ks*8+tig  ]);
                af[i][1]=__float_as_uint(smA[buf][r+8][ks*8+tig  ]);
                af[i][2]=__float_as_uint(smA[buf][r  ][ks*8+tig+4]);
                af[i][3]=__float_as_uint(smA[buf][r+8][ks*8+tig+4]);
            }
#pragma unroll
            for (int j=0;j<2;j++){
                int c = wn*16 + j*8 + gid;
                bf[j][0]=__float_as_uint(smB[buf][ks*8+tig  ][c]);
                bf[j][1]=__float_as_uint(smB[buf][ks*8+tig+4][c]);
            }
#pragma unroll
            for (int i=0;i<4;i++)
#pragma unroll
                for (int j=0;j<2;j++) mma_tf32(acc[i][j], af[i], bf[j]);
        }
    }
#undef ST_A
#undef ST_B

#pragma unroll
    for (int i=0;i<4;i++){
#pragma unroll
        for (int rr=0; rr<2; rr++){
            int t = t0 + wm*64 + i*16 + gid + rr*8;
            const float* prow = pb + (size_t)t*T_;
            for (int r=0;r<21;r++){
                int s = t + r - WIN_;
                if ((unsigned)s < (unsigned)T_){
                    float pv = prow[s];
#pragma unroll
                    for (int j=0;j<2;j++){
                        int d = wn*16 + j*8 + tig*2;
                        acc[i][j][rr*2+0] += pv*sErv[r*64 + d];
                        acc[i][j][rr*2+1] += pv*sErv[r*64 + d+1];
                    }
                }
            }
        }
    }

#pragma unroll
    for (int i=0;i<4;i++){
        int row = t0 + wm*64 + i*16 + gid;
#pragma unroll
        for (int j=0;j<2;j++){
            int d = wn*16 + j*8 + tig*2;
            float* c0 = CTX + (size_t)(b*C_ + h*64 + d)*T_;
            float* c1 = CTX + (size_t)(b*C_ + h*64 + d+1)*T_;
            c0[row]   = f2tfr(acc[i][j][0]);
            c1[row]   = f2tfr(acc[i][j][1]);
            c0[row+8] = f2tfr(acc[i][j][2]);
            c1[row+8] = f2tfr(acc[i][j][3]);
        }
    }
}

/* =========== K=3 conv GEMM: swizzled A + raw-row B staging =========== */
__launch_bounds__(256,2)
__global__ void gconv3p(const float* __restrict__ Xp, const float* __restrict__ Wm,
                        const float* __restrict__ bias, const float* __restrict__ mask,
                        float* __restrict__ Y, int Cin, int Cout,
                        int mode, int ktiles)
{
    const int n0 = blockIdx.x*128;
    const int m0 = blockIdx.y*128;
    const int bz = blockIdx.z;
    const int b    = (mode==1) ? (bz & 7) : bz;
    const int part = (mode==1) ? (bz >> 3) : 0;
    const int kOff = part*(ktiles*16);

    const int tid = threadIdx.x;
    const int lane = tid & 31, wid = tid >> 5;
    const int gid = lane >> 2, tig = lane & 3;
    const int wm = wid & 1, wn = wid >> 1;

    __shared__ float smA[3][2048];
    __shared__ float smX[3][6][136];

    const float* xpb = Xp + (size_t)b*Cin*TP_;
    const int Ktot = Cin*3;
    const int rB = tid/33, cB = tid - rB*33;

    float acc[4][4][4];
#pragma unroll
    for (int i=0;i<4;i++)
#pragma unroll
        for (int j=0;j<4;j++)
#pragma unroll
            for (int u=0;u<4;u++) acc[i][j][u]=0.f;

#define ST_A(st,K0) { const float* ap = Wm + (size_t)(m0>>7)*((size_t)Ktot<<7) + ((size_t)((K0)>>4)<<11) + (tid<<3); \
                      cp16(&smA[st][tid*8], ap); cp16(&smA[st][tid*8+4], ap+4); }
#define ST_B(st,K0) { if (tid < 198){ int cc0 = (K0)/3; \
                      const float* bp = xpb + (size_t)(cc0+rB)*TP_ + n0 + cB*4; \
                      cp16(&smX[st][rB][cB*4], bp); } }
    ST_A(0,kOff) ST_B(0,kOff) CP_COMMIT;
    ST_A(1,kOff+16) ST_B(1,kOff+16) CP_COMMIT;

    for (int kt=0; kt<ktiles; kt++){
        if (kt==ktiles-1) { CP_WAIT0; } else { CP_WAIT1; }
        __syncthreads();
        if (kt+2 < ktiles){ int st=(kt+2)%3; int K0=kOff+(kt+2)*16; ST_A(st,K0) ST_B(st,K0) CP_COMMIT; }
        const int buf = kt%3;
        const int Kbase = kOff + kt*16;
        const int cc0t = Kbase/3;
#pragma unroll
        for (int ks=0;ks<2;ks++){
            int kg0 = Kbase + ks*8 + tig;
            int kg1 = kg0 + 4;
            int q0 = kg0/3, q1 = kg1/3;
            int r0 = q0 - cc0t, k0 = kg0 - q0*3;
            int r1 = q1 - cc0t, k1 = kg1 - q1*3;
            unsigned af[4][4], bf[4][2];
            LOAD_AF(af, smA[buf], wm, ks, lane)
#pragma unroll
            for (int j=0;j<4;j++){
                int c = wn*32 + j*8 + gid;
                bf[j][0]=__float_as_uint(smX[buf][r0][c + k0]);
                bf[j][1]=__float_as_uint(smX[buf][r1][c + k1]);
            }
#pragma unroll
            for (int i=0;i<4;i++)
#pragma unroll
                for (int j=0;j<4;j++) mma_tf32(acc[i][j], af[i], bf[j]);
        }
    }
#undef ST_A
#undef ST_B

    if (mode==0){
        const float* mb = mask + b*T_;
#pragma unroll
        for (int i=0;i<4;i++){
            int row = m0 + wm*64 + i*16 + gid;
            float bv0 = bias[row], bv8 = bias[row+8];
            float* y0 = Y + (size_t)(b*Cout + row)*TP_ + 1;
            float* y8 = Y + (size_t)(b*Cout + row+8)*TP_ + 1;
#pragma unroll
            for (int j=0;j<4;j++){
                int col = n0 + wn*32 + j*8 + tig*2;
                float m0v = mb[col], m1v = mb[col+1];
                y0[col]   = f2tfr(fmaxf(acc[i][j][0]+bv0, 0.f)*m0v);
                y0[col+1] = f2tfr(fmaxf(acc[i][j][1]+bv0, 0.f)*m1v);
                y8[col]   = f2tfr(fmaxf(acc[i][j][2]+bv8, 0.f)*m0v);
                y8[col+1] = f2tfr(fmaxf(acc[i][j][3]+bv8, 0.f)*m1v);
            }
        }
    } else {
#pragma unroll
        for (int i=0;i<4;i++){
            int row = m0 + wm*64 + i*16 + gid;
            float* y0 = Y + (size_t)part*ELT_X + (size_t)(b*Cout + row)*T_;
            float* y8 = Y + (size_t)part*ELT_X + (size_t)(b*Cout + row+8)*T_;
#pragma unroll
            for (int j=0;j<4;j++){
                int col = n0 + wn*32 + j*8 + tig*2;
                *(float2*)(y0+col)=make_float2(acc[i][j][0], acc[i][j][1]);
                *(float2*)(y8+col)=make_float2(acc[i][j][2], acc[i][j][3]);
            }
        }
    }
}

/* ---------------- split-K reduce + bias + mask ---------------- */
__global__ void k_red(const float* __restrict__ P0, const float* __restrict__ bias,
                      const float* __restrict__ mask, float* __restrict__ Y)
{
    int i = blockIdx.x*256 + threadIdx.x;
    int t = i & (T_-1);
    int o = (i >> 9) & (C_-1);
    int b = i >> 18;
    Y[i] = (P0[i] + P0[(size_t)ELT_X + i] + bias[o]) * mask[b*T_ + t];
}

/* ---------------- banded relative-K logits (Qt layout) ---------------- */
__global__ void k_relband(const float* __restrict__ Qt, const float* __restrict__ erk,
                          float* __restrict__ P)
{
    const int bh = blockIdx.y;
    const int t = blockIdx.x*8 + (threadIdx.x>>5);
    const int lane = threadIdx.x & 31;
    const float* qr = Qt + ((size_t)bh*T_ + t)*64;
    float q0 = qr[lane];
    float q1 = qr[32+lane];
    float* prow = P + ((size_t)bh*T_ + t)*T_;
    for (int r=0;r<21;r++){
        float pd = q0*erk[r*64+lane] + q1*erk[r*64+32+lane];
#pragma unroll
        for (int o=16;o;o>>=1) pd += __shfl_xor_sync(0xffffffffu, pd, o);
        int s = t + r - WIN_;
        if (lane==0 && (unsigned)s < (unsigned)T_) prow[s] += pd;
    }
}

/* ---------------- row softmax with mask (rounded output) ---------------- */
__launch_bounds__(256)
__global__ void k_softmax(float* __restrict__ P, const float* __restrict__ mask)
{
    const int row = blockIdx.x;
    const int t  = row & (T_-1);
    const int bh = row >> 9;
    const int b  = bh >> 3;
    float* p = P + (size_t)row*T_;
    const float* mb = mask + b*T_;
    const int tid = threadIdx.x;
    const int lane = tid & 31, w = tid >> 5;
    const float mt = mb[t];
    float v0 = (mt*mb[tid]     != 0.f) ? p[tid]     : -1e4f;
    float v1 = (mt*mb[tid+256] != 0.f) ? p[tid+256] : -1e4f;
    __shared__ float red[8];
    float m = fmaxf(v0,v1);
#pragma unroll
    for (int o=16;o;o>>=1) m = fmaxf(m, __shfl_xor_sync(0xffffffffu, m, o));
    if (lane==0) red[w]=m;
    __syncthreads();
    float mx = red[0];
#pragma unroll
    for (int k2=1;k2<8;k2++) mx = fmaxf(mx, red[k2]);
    float e0 = expf(v0-mx), e1 = expf(v1-mx);
    float s = e0+e1;
#pragma unroll
    for (int o=16;o;o>>=1) s += __shfl_xor_sync(0xffffffffu, s, o);
    __syncthreads();
    if (lane==0) red[w]=s;
    __syncthreads();
    float tot = 0.f;
#pragma unroll
    for (int k2=0;k2<8;k2++) tot += red[k2];
    float inv = 1.f/tot;
    p[tid]=f2tfr(e0*inv); p[tid+256]=f2tfr(e1*inv);
}

/* ------- residual add + channel LN; optional padded-rounded / flat-rounded copies -- */
__launch_bounds__(512)
__global__ void k_addln(float* __restrict__ X, const float* __restrict__ Yv,
                        const float* __restrict__ gamma, const float* __restrict__ beta,
                        float* __restrict__ Xp, float* __restrict__ Xr,
                        const float* __restrict__ mask)
{
    const int b = blockIdx.y;
    const int tl = threadIdx.x & 31;
    const int slot = threadIdx.x >> 5;
    const int t = blockIdx.x*32 + tl;
    __shared__ float ssum[16][33];
    __shared__ float ssq[16][33];
    float vals[32];
    float s=0.f, q=0.f;
    size_t base = (size_t)b*C_*T_ + t;
#pragma unroll
    for (int u=0;u<32;u++){
        int c = slot*32+u;
        float v = X[base + (size_t)c*T_] + Yv[base + (size_t)c*T_];
        vals[u]=v; s+=v; q+=v*v;
    }
    ssum[slot][tl]=s; ssq[slot][tl]=q;
    __syncthreads();
    float m=0.f, vv=0.f;
#pragma unroll
    for (int k2=0;k2<16;k2++){ m+=ssum[k2][tl]; vv+=ssq[k2][tl]; }
    m *= (1.f/512.f);
    vv = vv*(1.f/512.f) - m*m;
    float r = rsqrtf(vv + 1e-5f);
    float mk = Xp ? mask[b*T_ + t] : 0.f;
#pragma unroll
    for (int u=0;u<32;u++){
        int c = slot*32+u;
        float o = (vals[u]-m)*r*gamma[c] + beta[c];
        X[base + (size_t)c*T_] = o;
        if (Xp) Xp[((size_t)(b*C_+c))*TP_ + t + 1] = f2tfr(o*mk);
        if (Xr) Xr[base + (size_t)c*T_] = f2tfr(o);
    }
}

/* ---------------- host orchestration ---------------- */
extern "C" void kernel_launch(void* const* d_in, const int* in_sizes, int n_in,
                              void* d_out, int out_size)
{
    (void)in_sizes; (void)n_in; (void)out_size;
    const float* x_in = (const float*)d_in[0];
    const float* mask = (const float*)d_in[1];
    const float* Wq  = (const float*)d_in[2];
    const float* bq  = (const float*)d_in[3];
    const float* Wk  = (const float*)d_in[4];
    const float* bk  = (const float*)d_in[5];
    const float* Wv  = (const float*)d_in[6];
    const float* bv  = (const float*)d_in[7];
    const float* Wo  = (const float*)d_in[8];
    const float* bo  = (const float*)d_in[9];
    const float* erk = (const float*)d_in[10];
    const float* erv = (const float*)d_in[11];
    const float* g1  = (const float*)d_in[12];
    const float* b1  = (const float*)d_in[13];
    const float* g2  = (const float*)d_in[14];
    const float* b2  = (const float*)d_in[15];
    const float* W1  = (const float*)d_in[16];
    const float* bf1 = (const float*)d_in[17];
    const float* W2  = (const float*)d_in[18];
    const float* bf2 = (const float*)d_in[19];

    float* pool = 0;
    cudaGetSymbolAddress((void**)&pool, g_pool);
    float* px  = pool;
    float* pxr = pool + (size_t)1*ELT_X;
    float* pq  = pool + (size_t)2*ELT_X;
    float* pk  = pool + (size_t)3*ELT_X;
    float* pv  = pool + (size_t)4*ELT_X;
    float* pc  = pool + (size_t)5*ELT_X;
    float* py  = pool + (size_t)6*ELT_X;
    float* pp  = pool + (size_t)7*ELT_X;
    float* pxp = pool + (size_t)7*ELT_X + ELT_P;
    float* php = pool + (size_t)7*ELT_X + ELT_P + ELT_XP;
    float* wqr = php + ELT_HP;
    float* wkr = wqr + WQKV;
    float* wvr = wkr + WQKV;
    float* wor = wvr + WQKV;
    float* w1r = wor + WQKV;
    float* w2r = w1r + WFF;

    size_t mszQ = (size_t)C_*C_;
    k_swizA<<<(unsigned)((WQKV+255)/256),256>>>(Wq, wqr, C_, mszQ, WQKV);
    k_swizA<<<(unsigned)((WQKV+255)/256),256>>>(Wk, wkr, C_, mszQ, WQKV);
    k_swizA<<<(unsigned)((WQKV+255)/256),256>>>(Wv, wvr, C_, mszQ, WQKV);
    k_swizA<<<(unsigned)((WQKV+255)/256),256>>>(Wo, wor, C_, mszQ, WQKV);
    k_swizA<<<(unsigned)((WFF+255)/256),256>>>(W1, w1r, C_*3, (size_t)F_*C_*3, WFF);
    k_swizA<<<(unsigned)((WFF+255)/256),256>>>(W2, w2r, F_*3, (size_t)C_*F_*3, WFF);

    k_maskmul2<<<ELT_X/256,256>>>(x_in, mask, px, pxr);
    k_zb<<<(B_*C_+B_*F_)/256,256>>>(pxp, php);

    for (int L=0;L<6;L++){
        g_qkv<<<dim3(T_/128, 12, B_),256>>>(pxr, wqr + (size_t)L*mszQ, wkr + (size_t)L*mszQ,
                                            wvr + (size_t)L*mszQ,
                                            bq+L*C_, bk+L*C_, bv+L*C_,
                                            pq, pk, pv);
        g_sc<<<dim3(T_/128, T_/128, B_*H_),256>>>(pq, pk, pp);
        k_relband<<<dim3(T_/8, B_*H_),256>>>(pq, erk + L*21*64, pp);
        k_softmax<<<B_*H_*T_,256>>>(pp, mask);
        g_ctx<<<dim3(T_/128, B_*H_),256>>>(pp, pv, erv + L*21*64, pc);
        g1x1<<<dim3(T_/128, C_/128, B_),256>>>(wor + (size_t)L*mszQ, pc, bo + L*C_, py);
        k_addln<<<dim3(T_/32,B_),512>>>(px, py, g1+L*C_, b1+L*C_, pxp, (float*)0, mask);

        gconv3p<<<dim3(T_/128, F_/128, B_),256>>>(pxp, w1r + (size_t)L*F_*C_*3, bf1+L*F_, mask,
                                                  php, C_, F_, 0, (C_*3)/16);
        gconv3p<<<dim3(T_/128, C_/128, 2*B_),256>>>(php, w2r + (size_t)L*C_*F_*3, bf2+L*C_, mask,
                                                    pq, F_, C_, 1, (F_*3)/32);
        k_red<<<ELT_X/256,256>>>(pq, bf2+L*C_, mask, py);
        k_addln<<<dim3(T_/32,B_),512>>>(px, py, g2+L*C_, b2+L*C_, (float*)0, pxr, mask);
    }
    k_maskmul<<<ELT_X/256,256>>>(px, mask, (float*)d_out);
}